// round 1
// baseline (speedup 1.0000x reference)
#include <cuda_runtime.h>
#include <math.h>

#define L 40
#define B 16
#define VSZ 10000
#define FDIM 512
#define HDIM 256
#define NPAIR 780            // triu pairs i<j
#define NROWS ((NPAIR + 1) * B)   // 12496; last 16 rows = init cell (0,0)

// ---------------- scratch (device globals; no runtime alloc allowed) ----------
__device__ float g_A1[L * B * HDIM];   // h @ Ww1[:F]
__device__ float g_A2[L * B * HDIM];   // h @ Ww1[F:]
__device__ float g_B1[L * B * HDIM];   // h @ Wt1[:F]
__device__ float g_B2[L * B * HDIM];   // h @ Wt1[F:]
__device__ float g_HID[NROWS * HDIM];  // tanh hidden for word model (12.8 MB)
__device__ float g_SH[NPAIR * B];      // log_sigmoid(-t)
__device__ float g_RE[NPAIR * B];      // log_sigmoid(t)
__device__ float g_WLP[NROWS];         // gathered - logsumexp  (incl. init row block)
__device__ float g_T[L * L * B];       // DP table

__device__ __forceinline__ void decode_pair(int p, int& i, int& j) {
    int ii = 0;
    while (p >= (L - 1) - ii) { p -= (L - 1) - ii; ++ii; }
    i = ii;
    j = ii + 1 + p;
}

__device__ __forceinline__ int pair_index(int i, int k) {
    // offset of row i in triu enumeration + (k - i - 1)
    return i * (L - 1) - (i * (i - 1)) / 2 + (k - i - 1);
}

__device__ __forceinline__ float logsig(float x) {
    return fminf(x, 0.f) - log1pf(__expf(-fabsf(x)));
}

// ---------------- 1) projection GEMMs: C[640,256] = h[640,512] @ Wslice[512,256]
// grid (10, 4, 4): z selects {A1, A2, B1, B2}
__global__ void proj_kernel(const float* __restrict__ h,
                            const float* __restrict__ Wt1,
                            const float* __restrict__ Ww1) {
    __shared__ float As[16][65];
    __shared__ float Bs[16][65];

    int which = blockIdx.z;
    const float* W = (which < 2) ? Ww1 : Wt1;
    const float* Wbase = W + ((which & 1) ? FDIM * HDIM : 0);
    float* C = (which == 0) ? g_A1 : (which == 1) ? g_A2 : (which == 2) ? g_B1 : g_B2;

    int tx = threadIdx.x;                 // 0..255
    int m0 = blockIdx.x * 64;
    int n0 = blockIdx.y * 64;
    int tm = (tx >> 4) * 4;
    int tn = (tx & 15) * 4;

    float acc[4][4];
#pragma unroll
    for (int a = 0; a < 4; a++)
#pragma unroll
        for (int c = 0; c < 4; c++) acc[a][c] = 0.f;

    for (int k0 = 0; k0 < FDIM; k0 += 16) {
#pragma unroll
        for (int l = tx; l < 64 * 16; l += 256) {
            int mm = l >> 4, kk = l & 15;
            As[kk][mm] = h[(m0 + mm) * FDIM + k0 + kk];
        }
#pragma unroll
        for (int l = tx; l < 16 * 64; l += 256) {
            int kk = l >> 6, nn = l & 63;
            Bs[kk][nn] = Wbase[(k0 + kk) * HDIM + n0 + nn];
        }
        __syncthreads();
#pragma unroll
        for (int kk = 0; kk < 16; ++kk) {
            float a0 = As[kk][tm], a1 = As[kk][tm + 1], a2 = As[kk][tm + 2], a3 = As[kk][tm + 3];
            float b0 = Bs[kk][tn], b1 = Bs[kk][tn + 1], b2 = Bs[kk][tn + 2], b3 = Bs[kk][tn + 3];
            acc[0][0] = fmaf(a0, b0, acc[0][0]); acc[0][1] = fmaf(a0, b1, acc[0][1]);
            acc[0][2] = fmaf(a0, b2, acc[0][2]); acc[0][3] = fmaf(a0, b3, acc[0][3]);
            acc[1][0] = fmaf(a1, b0, acc[1][0]); acc[1][1] = fmaf(a1, b1, acc[1][1]);
            acc[1][2] = fmaf(a1, b2, acc[1][2]); acc[1][3] = fmaf(a1, b3, acc[1][3]);
            acc[2][0] = fmaf(a2, b0, acc[2][0]); acc[2][1] = fmaf(a2, b1, acc[2][1]);
            acc[2][2] = fmaf(a2, b2, acc[2][2]); acc[2][3] = fmaf(a2, b3, acc[2][3]);
            acc[3][0] = fmaf(a3, b0, acc[3][0]); acc[3][1] = fmaf(a3, b1, acc[3][1]);
            acc[3][2] = fmaf(a3, b2, acc[3][2]); acc[3][3] = fmaf(a3, b3, acc[3][3]);
        }
        __syncthreads();
    }
#pragma unroll
    for (int a = 0; a < 4; a++)
#pragma unroll
        for (int c = 0; c < 4; c++)
            C[(m0 + tm + a) * HDIM + n0 + tn + c] = acc[a][c];
}

// ---------------- 2) transition MLP per pair -> SH, RE
__global__ void tpair_kernel(const float* __restrict__ bt1,
                             const float* __restrict__ Wt2,
                             const float* __restrict__ bt2) {
    __shared__ float red[8];
    int p = blockIdx.x;
    int tid = threadIdx.x;       // 256 = one thread per hidden unit
    int i, j;
    decode_pair(p, i, j);
    float b1v = bt1[tid];
    float w2v = Wt2[tid];
    int lane = tid & 31, wid = tid >> 5;

    for (int b = 0; b < B; ++b) {
        float hv = tanhf(g_B1[(i * B + b) * HDIM + tid] + g_B2[(j * B + b) * HDIM + tid] + b1v);
        float x = hv * w2v;
        x += __shfl_xor_sync(~0u, x, 16);
        x += __shfl_xor_sync(~0u, x, 8);
        x += __shfl_xor_sync(~0u, x, 4);
        x += __shfl_xor_sync(~0u, x, 2);
        x += __shfl_xor_sync(~0u, x, 1);
        if (lane == 0) red[wid] = x;
        __syncthreads();
        if (tid == 0) {
            float t = bt2[0];
#pragma unroll
            for (int w = 0; w < 8; ++w) t += red[w];
            g_SH[p * B + b] = logsig(-t);
            g_RE[p * B + b] = logsig(t);
        }
        __syncthreads();
    }
}

// ---------------- 3) word-model hidden: tanh(A1[i] + A2[j] + bw1)
__global__ void hidden_kernel(const float* __restrict__ bw1) {
    int r = blockIdx.x;          // 0..NROWS-1
    int tid = threadIdx.x;       // 256
    int p = r >> 4, b = r & 15;
    int i = 0, j = 0;
    if (p < NPAIR) decode_pair(p, i, j);
    float v = tanhf(g_A1[(i * B + b) * HDIM + tid] + g_A2[(j * B + b) * HDIM + tid] + bw1[tid]);
    g_HID[r * HDIM + tid] = v;
}

// ---------------- 4) fused layer-2 GEMM + online sumexp + target gather
#define MT 32                    // rows per CTA
__global__ void word_kernel(const float* __restrict__ Ww2,
                            const float* __restrict__ bw2,
                            const int* __restrict__ sentence) {
    __shared__ float hid_s[MT][HDIM];   // 32 KB
    __shared__ float red_s[MT][8];
    __shared__ float targ_s[MT];
    __shared__ int tgt_s[MT];

    int tid = threadIdx.x;              // 256
    int row0 = blockIdx.x * MT;

    for (int idx = tid; idx < MT * HDIM; idx += 256) {
        int r = idx >> 8, hh = idx & 255;
        int gr = row0 + r;
        hid_s[r][hh] = (gr < NROWS) ? g_HID[gr * HDIM + hh] : 0.f;
    }
    if (tid < MT) {
        int gr = row0 + tid;
        int t = 0;
        if (gr < NROWS) {
            int p = gr >> 4, b = gr & 15;
            if (p == NPAIR) {
                t = sentence[1 * B + b];               // init cell target
            } else {
                int i, j;
                decode_pair(p, i, j);
                int j1 = (j + 1 < L) ? (j + 1) : (L - 1);
                t = sentence[j1 * B + b];
            }
        }
        tgt_s[tid] = t;
        targ_s[tid] = 0.f;
    }
    __syncthreads();

    float s[MT];
#pragma unroll
    for (int r = 0; r < MT; r++) s[r] = 0.f;

    const int NCHUNK = (VSZ + 255) / 256;   // 40
    for (int chunk = 0; chunk < NCHUNK; ++chunk) {
        int v = chunk * 256 + tid;
        int vc = (v < VSZ) ? v : (VSZ - 1);
        float b2 = bw2[vc];
        float acc[MT];
#pragma unroll
        for (int r = 0; r < MT; r++) acc[r] = b2;

#pragma unroll 2
        for (int h4 = 0; h4 < HDIM / 4; ++h4) {
            int hh = h4 * 4;
            float w0 = Ww2[(hh + 0) * VSZ + vc];
            float w1 = Ww2[(hh + 1) * VSZ + vc];
            float w2 = Ww2[(hh + 2) * VSZ + vc];
            float w3 = Ww2[(hh + 3) * VSZ + vc];
#pragma unroll
            for (int r = 0; r < MT; r++) {
                float4 hv = *(const float4*)(&hid_s[r][hh]);
                acc[r] = fmaf(hv.x, w0, acc[r]);
                acc[r] = fmaf(hv.y, w1, acc[r]);
                acc[r] = fmaf(hv.z, w2, acc[r]);
                acc[r] = fmaf(hv.w, w3, acc[r]);
            }
        }
        if (v < VSZ) {
#pragma unroll
            for (int r = 0; r < MT; r++) {
                if (v == tgt_s[r]) targ_s[r] = acc[r];
                s[r] += __expf(acc[r]);
            }
        }
    }

    int lane = tid & 31, wid = tid >> 5;
#pragma unroll
    for (int r = 0; r < MT; r++) {
        float x = s[r];
        x += __shfl_xor_sync(~0u, x, 16);
        x += __shfl_xor_sync(~0u, x, 8);
        x += __shfl_xor_sync(~0u, x, 4);
        x += __shfl_xor_sync(~0u, x, 2);
        x += __shfl_xor_sync(~0u, x, 1);
        if (lane == 0) red_s[r][wid] = x;
    }
    __syncthreads();
    if (tid < MT) {
        float tot = 0.f;
#pragma unroll
        for (int w = 0; w < 8; ++w) tot += red_s[tid][w];
        int gr = row0 + tid;
        if (gr < NROWS) g_WLP[gr] = targ_s[tid] - logf(tot);
    }
}

// ---------------- 5) CKY DP, single persistent CTA
__global__ void dp_kernel(float* __restrict__ out) {
    int tid = threadIdx.x;       // 640 = 40*16
    int b = tid & 15, i = tid >> 4;

    // width-1 init
    if (i == 0) {
        g_T[(0 * L + 1) * B + b] = g_WLP[NPAIR * B + b];
    } else if (i <= L - 2 - 1 + 1 && i <= 38 && i >= 1) {
        if (i + 1 <= L - 1) g_T[(i * L + (i + 1)) * B + b] = 0.f;
    }
    __syncthreads();

    for (int gap = 2; gap <= L - 1; ++gap) {
        int n_i = L - gap;
        float result = 0.f;
        int j = i + gap;
        if (i < n_i) {
            float m = -1e30f;
            for (int k = i + 1; k < j; ++k) {
                int pik = pair_index(i, k);
                int pkj = pair_index(k, j);
                float sc = g_T[(i * L + k) * B + b] + g_T[(k * L + j) * B + b]
                         + g_SH[pik * B + b] + g_WLP[pik * B + b]
                         + g_RE[pkj * B + b];
                m = fmaxf(m, sc);
            }
            float ssum = 0.f;
            for (int k = i + 1; k < j; ++k) {
                int pik = pair_index(i, k);
                int pkj = pair_index(k, j);
                float sc = g_T[(i * L + k) * B + b] + g_T[(k * L + j) * B + b]
                         + g_SH[pik * B + b] + g_WLP[pik * B + b]
                         + g_RE[pkj * B + b];
                ssum += __expf(sc - m);
            }
            result = m + logf(ssum);
        }
        if (i < n_i) g_T[(i * L + j) * B + b] = result;
        __syncthreads();
    }

    if (tid < B) out[tid] = g_T[(0 * L + (L - 1)) * B + tid];
}

// ---------------- launcher ----------------
extern "C" void kernel_launch(void* const* d_in, const int* in_sizes, int n_in,
                              void* d_out, int out_size) {
    const float* h        = (const float*)d_in[0];
    const int*   sentence = (const int*)d_in[1];
    const float* Wt1      = (const float*)d_in[2];
    const float* bt1      = (const float*)d_in[3];
    const float* Wt2      = (const float*)d_in[4];
    const float* bt2      = (const float*)d_in[5];
    const float* Ww1      = (const float*)d_in[6];
    const float* bw1      = (const float*)d_in[7];
    const float* Ww2      = (const float*)d_in[8];
    const float* bw2      = (const float*)d_in[9];
    float* out = (float*)d_out;

    proj_kernel<<<dim3(10, 4, 4), 256>>>(h, Wt1, Ww1);
    tpair_kernel<<<NPAIR, 256>>>(bt1, Wt2, bt2);
    hidden_kernel<<<NROWS, 256>>>(bw1);
    word_kernel<<<(NROWS + MT - 1) / MT, 256>>>(Ww2, bw2, sentence);
    dp_kernel<<<1, 640>>>(out);
}

// round 3
// speedup vs baseline: 1.4306x; 1.4306x over previous
#include <cuda_runtime.h>
#include <math.h>

#define L 40
#define B 16
#define VSZ 10000
#define FDIM 512
#define HDIM 256
#define NPAIR 780                 // triu pairs i<j
#define NROWS ((NPAIR + 1) * B)   // 12496; last 16 rows = init cell (0,0)

#define MT 44                     // rows per CTA: 284 * 44 == 12496 exactly
#define NPR (MT / 2)              // 22 packed row-pairs
#define NGRID (NROWS / MT)        // 284

// ---------------- scratch (device globals; no runtime alloc allowed) ----------
__device__ float g_A1[L * B * HDIM];   // h @ Ww1[:F]
__device__ float g_A2[L * B * HDIM];   // h @ Ww1[F:]
__device__ float g_B1[L * B * HDIM];   // h @ Wt1[:F]
__device__ float g_B2[L * B * HDIM];   // h @ Wt1[F:]
__device__ float g_HID[NROWS * HDIM];  // tanh hidden for word model
__device__ float g_SH[NPAIR * B];      // log_sigmoid(-t)
__device__ float g_RE[NPAIR * B];      // log_sigmoid(t)
__device__ float g_WLP[NROWS];         // gathered - logsumexp (incl. init rows)
__device__ float g_T[L * L * B];       // DP table

__device__ __forceinline__ void decode_pair(int p, int& i, int& j) {
    int ii = 0;
    while (p >= (L - 1) - ii) { p -= (L - 1) - ii; ++ii; }
    i = ii;
    j = ii + 1 + p;
}

__device__ __forceinline__ int pair_index(int i, int k) {
    return i * (L - 1) - (i * (i - 1)) / 2 + (k - i - 1);
}

__device__ __forceinline__ float logsig(float x) {
    return fminf(x, 0.f) - log1pf(__expf(-fabsf(x)));
}

#define FMA_F32X2(d, a, b, c) \
    asm("fma.rn.f32x2 %0, %1, %2, %3;" : "=l"(d) : "l"(a), "l"(b), "l"(c))
#define SPLAT_F32X2(d, f) \
    asm("mov.b64 %0, {%1, %1};" : "=l"(d) : "f"(f))
#define UNPACK_F32X2(lo, hi, in) \
    asm("mov.b64 {%0, %1}, %2;" : "=f"(lo), "=f"(hi) : "l"(in))

// ---------------- 1) projection GEMMs: C[640,256] = h[640,512] @ Wslice[512,256]
__global__ void proj_kernel(const float* __restrict__ h,
                            const float* __restrict__ Wt1,
                            const float* __restrict__ Ww1) {
    __shared__ float As[16][65];
    __shared__ float Bs[16][65];

    int which = blockIdx.z;
    const float* W = (which < 2) ? Ww1 : Wt1;
    const float* Wbase = W + ((which & 1) ? FDIM * HDIM : 0);
    float* C = (which == 0) ? g_A1 : (which == 1) ? g_A2 : (which == 2) ? g_B1 : g_B2;

    int tx = threadIdx.x;
    int m0 = blockIdx.x * 64;
    int n0 = blockIdx.y * 64;
    int tm = (tx >> 4) * 4;
    int tn = (tx & 15) * 4;

    float acc[4][4];
#pragma unroll
    for (int a = 0; a < 4; a++)
#pragma unroll
        for (int c = 0; c < 4; c++) acc[a][c] = 0.f;

    for (int k0 = 0; k0 < FDIM; k0 += 16) {
#pragma unroll
        for (int l = tx; l < 64 * 16; l += 256) {
            int mm = l >> 4, kk = l & 15;
            As[kk][mm] = h[(m0 + mm) * FDIM + k0 + kk];
        }
#pragma unroll
        for (int l = tx; l < 16 * 64; l += 256) {
            int kk = l >> 6, nn = l & 63;
            Bs[kk][nn] = Wbase[(k0 + kk) * HDIM + n0 + nn];
        }
        __syncthreads();
#pragma unroll
        for (int kk = 0; kk < 16; ++kk) {
            float a0 = As[kk][tm], a1 = As[kk][tm + 1], a2 = As[kk][tm + 2], a3 = As[kk][tm + 3];
            float b0 = Bs[kk][tn], b1 = Bs[kk][tn + 1], b2 = Bs[kk][tn + 2], b3 = Bs[kk][tn + 3];
            acc[0][0] = fmaf(a0, b0, acc[0][0]); acc[0][1] = fmaf(a0, b1, acc[0][1]);
            acc[0][2] = fmaf(a0, b2, acc[0][2]); acc[0][3] = fmaf(a0, b3, acc[0][3]);
            acc[1][0] = fmaf(a1, b0, acc[1][0]); acc[1][1] = fmaf(a1, b1, acc[1][1]);
            acc[1][2] = fmaf(a1, b2, acc[1][2]); acc[1][3] = fmaf(a1, b3, acc[1][3]);
            acc[2][0] = fmaf(a2, b0, acc[2][0]); acc[2][1] = fmaf(a2, b1, acc[2][1]);
            acc[2][2] = fmaf(a2, b2, acc[2][2]); acc[2][3] = fmaf(a2, b3, acc[2][3]);
            acc[3][0] = fmaf(a3, b0, acc[3][0]); acc[3][1] = fmaf(a3, b1, acc[3][1]);
            acc[3][2] = fmaf(a3, b2, acc[3][2]); acc[3][3] = fmaf(a3, b3, acc[3][3]);
        }
        __syncthreads();
    }
#pragma unroll
    for (int a = 0; a < 4; a++)
#pragma unroll
        for (int c = 0; c < 4; c++)
            C[(m0 + tm + a) * HDIM + n0 + tn + c] = acc[a][c];
}

// ---------------- 2) transition MLP per pair -> SH, RE
__global__ void tpair_kernel(const float* __restrict__ bt1,
                             const float* __restrict__ Wt2,
                             const float* __restrict__ bt2) {
    __shared__ float red[8];
    int p = blockIdx.x;
    int tid = threadIdx.x;
    int i, j;
    decode_pair(p, i, j);
    float b1v = bt1[tid];
    float w2v = Wt2[tid];
    int lane = tid & 31, wid = tid >> 5;

    for (int b = 0; b < B; ++b) {
        float hv = tanhf(g_B1[(i * B + b) * HDIM + tid] + g_B2[(j * B + b) * HDIM + tid] + b1v);
        float x = hv * w2v;
        x += __shfl_xor_sync(~0u, x, 16);
        x += __shfl_xor_sync(~0u, x, 8);
        x += __shfl_xor_sync(~0u, x, 4);
        x += __shfl_xor_sync(~0u, x, 2);
        x += __shfl_xor_sync(~0u, x, 1);
        if (lane == 0) red[wid] = x;
        __syncthreads();
        if (tid == 0) {
            float t = bt2[0];
#pragma unroll
            for (int w = 0; w < 8; ++w) t += red[w];
            g_SH[p * B + b] = logsig(-t);
            g_RE[p * B + b] = logsig(t);
        }
        __syncthreads();
    }
}

// ---------------- 3) word-model hidden: tanh(A1[i] + A2[j] + bw1)
__global__ void hidden_kernel(const float* __restrict__ bw1) {
    int r = blockIdx.x;
    int tid = threadIdx.x;
    int p = r >> 4, b = r & 15;
    int i = 0, j = 0;
    if (p < NPAIR) decode_pair(p, i, j);
    float v = tanhf(g_A1[(i * B + b) * HDIM + tid] + g_A2[(j * B + b) * HDIM + tid] + bw1[tid]);
    g_HID[r * HDIM + tid] = v;
}

// ---------------- 4) fused layer-2 GEMM (packed f32x2) + online sumexp + gather
__global__ __launch_bounds__(256)
void word_kernel(const float* __restrict__ Ww2,
                 const float* __restrict__ bw2,
                 const int* __restrict__ sentence) {
    // transposed packed hidden tile: hid_p[h][r], r fastest (44 floats per h)
    __shared__ float hid_p[HDIM * MT];         // 45056 B
    __shared__ float red_s[MT][8];
    __shared__ float targ_s[MT];
    __shared__ int tgt_s[MT];

    int tid = threadIdx.x;                     // 256
    int row0 = blockIdx.x * MT;

    // load + transpose hidden tile (coalesced global reads)
    for (int idx = tid; idx < MT * HDIM; idx += 256) {
        int r = idx >> 8, hh = idx & 255;      // r: 0..43
        hid_p[hh * MT + r] = g_HID[(row0 + r) * HDIM + hh];
    }
    if (tid < MT) {
        int gr = row0 + tid;
        int p = gr >> 4, b = gr & 15;
        int t;
        if (p == NPAIR) {
            t = sentence[1 * B + b];
        } else {
            int i, j;
            decode_pair(p, i, j);
            int j1 = (j + 1 < L) ? (j + 1) : (L - 1);
            t = sentence[j1 * B + b];
        }
        tgt_s[tid] = t;
        targ_s[tid] = 0.f;
    }
    __syncthreads();

    float2 s[NPR];
#pragma unroll
    for (int p = 0; p < NPR; p++) s[p] = make_float2(0.f, 0.f);

    const int NCHUNK = (VSZ + 255) / 256;      // 40
    for (int chunk = 0; chunk < NCHUNK; ++chunk) {
        int v = chunk * 256 + tid;
        int vc = (v < VSZ) ? v : (VSZ - 1);
        float b2 = bw2[vc];

        unsigned long long acc2[NPR];
        unsigned long long binit;
        SPLAT_F32X2(binit, b2);
#pragma unroll
        for (int p = 0; p < NPR; p++) acc2[p] = binit;

        const float* wcol = Ww2 + vc;
#pragma unroll 4
        for (int k = 0; k < HDIM; ++k) {
            float wv = __ldg(wcol + k * VSZ);
            unsigned long long ww;
            SPLAT_F32X2(ww, wv);
            const ulonglong2* hp = (const ulonglong2*)(hid_p + k * MT);
#pragma unroll
            for (int q = 0; q < NPR / 2; ++q) {      // 11 x ld.shared.v4 (broadcast)
                ulonglong2 hh = hp[q];
                FMA_F32X2(acc2[2 * q + 0], hh.x, ww, acc2[2 * q + 0]);
                FMA_F32X2(acc2[2 * q + 1], hh.y, ww, acc2[2 * q + 1]);
            }
        }

        if (v < VSZ) {
#pragma unroll
            for (int p = 0; p < NPR; p++) {
                float alo, ahi;
                UNPACK_F32X2(alo, ahi, acc2[p]);
                s[p].x += __expf(alo);
                s[p].y += __expf(ahi);
                if (v == tgt_s[2 * p + 0]) targ_s[2 * p + 0] = alo;
                if (v == tgt_s[2 * p + 1]) targ_s[2 * p + 1] = ahi;
            }
        }
    }

    int lane = tid & 31, wid = tid >> 5;
#pragma unroll
    for (int p = 0; p < NPR; p++) {
#pragma unroll
        for (int half = 0; half < 2; ++half) {
            float x = half ? s[p].y : s[p].x;
            x += __shfl_xor_sync(~0u, x, 16);
            x += __shfl_xor_sync(~0u, x, 8);
            x += __shfl_xor_sync(~0u, x, 4);
            x += __shfl_xor_sync(~0u, x, 2);
            x += __shfl_xor_sync(~0u, x, 1);
            if (lane == 0) red_s[2 * p + half][wid] = x;
        }
    }
    __syncthreads();
    if (tid < MT) {
        float tot = 0.f;
#pragma unroll
        for (int w = 0; w < 8; ++w) tot += red_s[tid][w];
        g_WLP[row0 + tid] = targ_s[tid] - logf(tot);
    }
}

// ---------------- 5) CKY DP, single persistent CTA
__global__ void dp_kernel(float* __restrict__ out) {
    int tid = threadIdx.x;       // 640 = 40*16
    int b = tid & 15, i = tid >> 4;

    if (i == 0) {
        g_T[(0 * L + 1) * B + b] = g_WLP[NPAIR * B + b];
    } else if (i >= 1 && i <= 38) {
        g_T[(i * L + (i + 1)) * B + b] = 0.f;
    }
    __syncthreads();

    for (int gap = 2; gap <= L - 1; ++gap) {
        int n_i = L - gap;
        float result = 0.f;
        int j = i + gap;
        if (i < n_i) {
            float m = -1e30f;
            for (int k = i + 1; k < j; ++k) {
                int pik = pair_index(i, k);
                int pkj = pair_index(k, j);
                float sc = g_T[(i * L + k) * B + b] + g_T[(k * L + j) * B + b]
                         + g_SH[pik * B + b] + g_WLP[pik * B + b]
                         + g_RE[pkj * B + b];
                m = fmaxf(m, sc);
            }
            float ssum = 0.f;
            for (int k = i + 1; k < j; ++k) {
                int pik = pair_index(i, k);
                int pkj = pair_index(k, j);
                float sc = g_T[(i * L + k) * B + b] + g_T[(k * L + j) * B + b]
                         + g_SH[pik * B + b] + g_WLP[pik * B + b]
                         + g_RE[pkj * B + b];
                ssum += __expf(sc - m);
            }
            result = m + logf(ssum);
        }
        if (i < n_i) g_T[(i * L + j) * B + b] = result;
        __syncthreads();
    }

    if (tid < B) out[tid] = g_T[(0 * L + (L - 1)) * B + tid];
}

// ---------------- launcher ----------------
extern "C" void kernel_launch(void* const* d_in, const int* in_sizes, int n_in,
                              void* d_out, int out_size) {
    const float* h        = (const float*)d_in[0];
    const int*   sentence = (const int*)d_in[1];
    const float* Wt1      = (const float*)d_in[2];
    const float* bt1      = (const float*)d_in[3];
    const float* Wt2      = (const float*)d_in[4];
    const float* bt2      = (const float*)d_in[5];
    const float* Ww1      = (const float*)d_in[6];
    const float* bw1      = (const float*)d_in[7];
    const float* Ww2      = (const float*)d_in[8];
    const float* bw2      = (const float*)d_in[9];
    float* out = (float*)d_out;

    proj_kernel<<<dim3(10, 4, 4), 256>>>(h, Wt1, Ww1);
    tpair_kernel<<<NPAIR, 256>>>(bt1, Wt2, bt2);
    hidden_kernel<<<NROWS, 256>>>(bw1);
    word_kernel<<<NGRID, 256>>>(Ww2, bw2, sentence);
    dp_kernel<<<1, 640>>>(out);
}

// round 4
// speedup vs baseline: 1.8019x; 1.2595x over previous
#include <cuda_runtime.h>
#include <math.h>

#define L 40
#define B 16
#define VSZ 10000
#define FDIM 512
#define HDIM 256
#define NPAIR 780                 // triu pairs i<j
#define NROWS ((NPAIR + 1) * B)   // 12496; last 16 rows = init cell (0,0)

#define MT 16                     // rows per CTA == one pair's batch; grid = 781
#define NPR (MT / 2)              // 8 packed row-pairs
#define VT 4                      // vocab columns per thread
#define NGRID (NROWS / MT)        // 781
#define VTILE (256 * VT)          // 1024 vocab per CTA pass
#define NCHUNK ((VSZ + VTILE - 1) / VTILE)   // 10

// ---------------- scratch (device globals; no runtime alloc allowed) ----------
__device__ float g_A1[L * B * HDIM];   // h @ Ww1[:F]
__device__ float g_A2[L * B * HDIM];   // h @ Ww1[F:]
__device__ float g_B1[L * B * HDIM];   // h @ Wt1[:F]
__device__ float g_B2[L * B * HDIM];   // h @ Wt1[F:]
__device__ float g_HID[NROWS * HDIM];  // tanh hidden for word model
__device__ float g_SH[NPAIR * B];      // log_sigmoid(-t)
__device__ float g_RE[NPAIR * B];      // log_sigmoid(t)
__device__ float g_WLP[NROWS];         // gathered - logsumexp (incl. init rows)
__device__ float g_T[L * L * B];       // DP table

__device__ __forceinline__ void decode_pair(int p, int& i, int& j) {
    int ii = 0;
    while (p >= (L - 1) - ii) { p -= (L - 1) - ii; ++ii; }
    i = ii;
    j = ii + 1 + p;
}

__device__ __forceinline__ int pair_index(int i, int k) {
    return i * (L - 1) - (i * (i - 1)) / 2 + (k - i - 1);
}

__device__ __forceinline__ float logsig(float x) {
    return fminf(x, 0.f) - log1pf(__expf(-fabsf(x)));
}

#define FMA_F32X2(d, a, b, c) \
    asm("fma.rn.f32x2 %0, %1, %2, %3;" : "=l"(d) : "l"(a), "l"(b), "l"(c))
#define SPLAT_F32X2(d, f) \
    asm("mov.b64 %0, {%1, %1};" : "=l"(d) : "f"(f))
#define UNPACK_F32X2(lo, hi, in) \
    asm("mov.b64 {%0, %1}, %2;" : "=f"(lo), "=f"(hi) : "l"(in))

// ---------------- 1) projection GEMMs: C[640,256] = h[640,512] @ Wslice[512,256]
__global__ void proj_kernel(const float* __restrict__ h,
                            const float* __restrict__ Wt1,
                            const float* __restrict__ Ww1) {
    __shared__ float As[16][65];
    __shared__ float Bs[16][65];

    int which = blockIdx.z;
    const float* W = (which < 2) ? Ww1 : Wt1;
    const float* Wbase = W + ((which & 1) ? FDIM * HDIM : 0);
    float* C = (which == 0) ? g_A1 : (which == 1) ? g_A2 : (which == 2) ? g_B1 : g_B2;

    int tx = threadIdx.x;
    int m0 = blockIdx.x * 64;
    int n0 = blockIdx.y * 64;
    int tm = (tx >> 4) * 4;
    int tn = (tx & 15) * 4;

    float acc[4][4];
#pragma unroll
    for (int a = 0; a < 4; a++)
#pragma unroll
        for (int c = 0; c < 4; c++) acc[a][c] = 0.f;

    for (int k0 = 0; k0 < FDIM; k0 += 16) {
#pragma unroll
        for (int l = tx; l < 64 * 16; l += 256) {
            int mm = l >> 4, kk = l & 15;
            As[kk][mm] = h[(m0 + mm) * FDIM + k0 + kk];
        }
#pragma unroll
        for (int l = tx; l < 16 * 64; l += 256) {
            int kk = l >> 6, nn = l & 63;
            Bs[kk][nn] = Wbase[(k0 + kk) * HDIM + n0 + nn];
        }
        __syncthreads();
#pragma unroll
        for (int kk = 0; kk < 16; ++kk) {
            float a0 = As[kk][tm], a1 = As[kk][tm + 1], a2 = As[kk][tm + 2], a3 = As[kk][tm + 3];
            float b0 = Bs[kk][tn], b1 = Bs[kk][tn + 1], b2 = Bs[kk][tn + 2], b3 = Bs[kk][tn + 3];
            acc[0][0] = fmaf(a0, b0, acc[0][0]); acc[0][1] = fmaf(a0, b1, acc[0][1]);
            acc[0][2] = fmaf(a0, b2, acc[0][2]); acc[0][3] = fmaf(a0, b3, acc[0][3]);
            acc[1][0] = fmaf(a1, b0, acc[1][0]); acc[1][1] = fmaf(a1, b1, acc[1][1]);
            acc[1][2] = fmaf(a1, b2, acc[1][2]); acc[1][3] = fmaf(a1, b3, acc[1][3]);
            acc[2][0] = fmaf(a2, b0, acc[2][0]); acc[2][1] = fmaf(a2, b1, acc[2][1]);
            acc[2][2] = fmaf(a2, b2, acc[2][2]); acc[2][3] = fmaf(a2, b3, acc[2][3]);
            acc[3][0] = fmaf(a3, b0, acc[3][0]); acc[3][1] = fmaf(a3, b1, acc[3][1]);
            acc[3][2] = fmaf(a3, b2, acc[3][2]); acc[3][3] = fmaf(a3, b3, acc[3][3]);
        }
        __syncthreads();
    }
#pragma unroll
    for (int a = 0; a < 4; a++)
#pragma unroll
        for (int c = 0; c < 4; c++)
            C[(m0 + tm + a) * HDIM + n0 + tn + c] = acc[a][c];
}

// ---------------- 2) transition MLP per pair -> SH, RE (warp-local, no bar.sync)
__global__ void tpair_kernel(const float* __restrict__ bt1,
                             const float* __restrict__ Wt2,
                             const float* __restrict__ bt2) {
    int p = blockIdx.x;
    int tid = threadIdx.x;           // 256
    int wid = tid >> 5, lane = tid & 31;
    int i, j;
    decode_pair(p, i, j);

#pragma unroll
    for (int sub = 0; sub < 2; ++sub) {
        int b = wid * 2 + sub;       // 8 warps x 2 = 16
        const float* r1 = g_B1 + (i * B + b) * HDIM;
        const float* r2 = g_B2 + (j * B + b) * HDIM;
        float acc = 0.f;
#pragma unroll
        for (int hh = lane; hh < HDIM; hh += 32) {
            float hv = tanhf(r1[hh] + r2[hh] + bt1[hh]);
            acc = fmaf(hv, Wt2[hh], acc);
        }
        acc += __shfl_xor_sync(~0u, acc, 16);
        acc += __shfl_xor_sync(~0u, acc, 8);
        acc += __shfl_xor_sync(~0u, acc, 4);
        acc += __shfl_xor_sync(~0u, acc, 2);
        acc += __shfl_xor_sync(~0u, acc, 1);
        if (lane == 0) {
            float t = acc + bt2[0];
            g_SH[p * B + b] = logsig(-t);
            g_RE[p * B + b] = logsig(t);
        }
    }
}

// ---------------- 3) word-model hidden: tanh(A1[i] + A2[j] + bw1)
__global__ void hidden_kernel(const float* __restrict__ bw1) {
    int r = blockIdx.x;
    int tid = threadIdx.x;
    int p = r >> 4, b = r & 15;
    int i = 0, j = 0;
    if (p < NPAIR) decode_pair(p, i, j);
    float v = tanhf(g_A1[(i * B + b) * HDIM + tid] + g_A2[(j * B + b) * HDIM + tid] + bw1[tid]);
    g_HID[r * HDIM + tid] = v;
}

// ---------------- 4) fused layer-2 GEMM (f32x2, MT=16 x VT=4) + sumexp + gather
__global__ __launch_bounds__(256, 2)
void word_kernel(const float* __restrict__ Ww2,
                 const float* __restrict__ bw2,
                 const int* __restrict__ sentence) {
    // transposed packed hidden tile: hid_p[h][r], r fastest (16 floats per h) = 16 KB
    __shared__ float hid_p[HDIM * MT];
    __shared__ float red_s[MT][8];
    __shared__ float targ_s[MT];
    __shared__ int tgt_s[MT];

    int tid = threadIdx.x;                     // 256
    int row0 = blockIdx.x * MT;
    int p0 = blockIdx.x;                       // pair index (MT == B)

    // load + transpose hidden tile
    for (int idx = tid; idx < MT * HDIM; idx += 256) {
        int r = idx >> 8, hh = idx & 255;
        hid_p[hh * MT + r] = g_HID[(row0 + r) * HDIM + hh];
    }
    if (tid < MT) {
        int b = tid;
        int t;
        if (p0 == NPAIR) {
            t = sentence[1 * B + b];
        } else {
            int i, j;
            decode_pair(p0, i, j);
            int j1 = (j + 1 < L) ? (j + 1) : (L - 1);
            t = sentence[j1 * B + b];
        }
        tgt_s[tid] = t;
        targ_s[tid] = 0.f;
    }
    __syncthreads();

    float2 s[NPR];
#pragma unroll
    for (int p = 0; p < NPR; p++) s[p] = make_float2(0.f, 0.f);

    for (int chunk = 0; chunk < NCHUNK; ++chunk) {
        int vbase = chunk * VTILE + tid;
        int vv[VT], vc[VT];
#pragma unroll
        for (int u = 0; u < VT; ++u) {
            vv[u] = vbase + u * 256;
            vc[u] = (vv[u] < VSZ) ? vv[u] : (VSZ - 1);
        }

        unsigned long long acc2[VT][NPR];
#pragma unroll
        for (int u = 0; u < VT; ++u) {
            unsigned long long binit;
            SPLAT_F32X2(binit, bw2[vc[u]]);
#pragma unroll
            for (int p = 0; p < NPR; p++) acc2[u][p] = binit;
        }

#pragma unroll 2
        for (int k = 0; k < HDIM; ++k) {
            unsigned long long ww[VT];
#pragma unroll
            for (int u = 0; u < VT; ++u) {
                float wv = __ldg(Ww2 + k * VSZ + vc[u]);
                SPLAT_F32X2(ww[u], wv);
            }
            const ulonglong2* hp = (const ulonglong2*)(hid_p + k * MT);
#pragma unroll
            for (int q = 0; q < NPR / 2; ++q) {          // 4 x ld.shared.v4 (broadcast)
                ulonglong2 hh = hp[q];
#pragma unroll
                for (int u = 0; u < VT; ++u) {
                    FMA_F32X2(acc2[u][2 * q + 0], hh.x, ww[u], acc2[u][2 * q + 0]);
                    FMA_F32X2(acc2[u][2 * q + 1], hh.y, ww[u], acc2[u][2 * q + 1]);
                }
            }
        }

#pragma unroll
        for (int u = 0; u < VT; ++u) {
            if (vv[u] < VSZ) {
#pragma unroll
                for (int p = 0; p < NPR; p++) {
                    float alo, ahi;
                    UNPACK_F32X2(alo, ahi, acc2[u][p]);
                    s[p].x += __expf(alo);
                    s[p].y += __expf(ahi);
                    if (vv[u] == tgt_s[2 * p + 0]) targ_s[2 * p + 0] = alo;
                    if (vv[u] == tgt_s[2 * p + 1]) targ_s[2 * p + 1] = ahi;
                }
            }
        }
    }

    int lane = tid & 31, wid = tid >> 5;
#pragma unroll
    for (int p = 0; p < NPR; p++) {
#pragma unroll
        for (int half = 0; half < 2; ++half) {
            float x = half ? s[p].y : s[p].x;
            x += __shfl_xor_sync(~0u, x, 16);
            x += __shfl_xor_sync(~0u, x, 8);
            x += __shfl_xor_sync(~0u, x, 4);
            x += __shfl_xor_sync(~0u, x, 2);
            x += __shfl_xor_sync(~0u, x, 1);
            if (lane == 0) red_s[2 * p + half][wid] = x;
        }
    }
    __syncthreads();
    if (tid < MT) {
        float tot = 0.f;
#pragma unroll
        for (int w = 0; w < 8; ++w) tot += red_s[tid][w];
        g_WLP[row0 + tid] = targ_s[tid] - logf(tot);
    }
}

// ---------------- 5) CKY DP, single persistent CTA
__global__ void dp_kernel(float* __restrict__ out) {
    int tid = threadIdx.x;       // 640 = 40*16
    int b = tid & 15, i = tid >> 4;

    if (i == 0) {
        g_T[(0 * L + 1) * B + b] = g_WLP[NPAIR * B + b];
    } else if (i >= 1 && i <= 38) {
        g_T[(i * L + (i + 1)) * B + b] = 0.f;
    }
    __syncthreads();

    for (int gap = 2; gap <= L - 1; ++gap) {
        int n_i = L - gap;
        float result = 0.f;
        int j = i + gap;
        if (i < n_i) {
            float m = -1e30f;
            for (int k = i + 1; k < j; ++k) {
                int pik = pair_index(i, k);
                int pkj = pair_index(k, j);
                float sc = g_T[(i * L + k) * B + b] + g_T[(k * L + j) * B + b]
                         + g_SH[pik * B + b] + g_WLP[pik * B + b]
                         + g_RE[pkj * B + b];
                m = fmaxf(m, sc);
            }
            float ssum = 0.f;
            for (int k = i + 1; k < j; ++k) {
                int pik = pair_index(i, k);
                int pkj = pair_index(k, j);
                float sc = g_T[(i * L + k) * B + b] + g_T[(k * L + j) * B + b]
                         + g_SH[pik * B + b] + g_WLP[pik * B + b]
                         + g_RE[pkj * B + b];
                ssum += __expf(sc - m);
            }
            result = m + logf(ssum);
        }
        if (i < n_i) g_T[(i * L + j) * B + b] = result;
        __syncthreads();
    }

    if (tid < B) out[tid] = g_T[(0 * L + (L - 1)) * B + tid];
}

// ---------------- launcher ----------------
extern "C" void kernel_launch(void* const* d_in, const int* in_sizes, int n_in,
                              void* d_out, int out_size) {
    const float* h        = (const float*)d_in[0];
    const int*   sentence = (const int*)d_in[1];
    const float* Wt1      = (const float*)d_in[2];
    const float* bt1      = (const float*)d_in[3];
    const float* Wt2      = (const float*)d_in[4];
    const float* bt2      = (const float*)d_in[5];
    const float* Ww1      = (const float*)d_in[6];
    const float* bw1      = (const float*)d_in[7];
    const float* Ww2      = (const float*)d_in[8];
    const float* bw2      = (const float*)d_in[9];
    float* out = (float*)d_out;

    proj_kernel<<<dim3(10, 4, 4), 256>>>(h, Wt1, Ww1);
    tpair_kernel<<<NPAIR, 256>>>(bt1, Wt2, bt2);
    hidden_kernel<<<NROWS, 256>>>(bw1);
    word_kernel<<<NGRID, 256>>>(Ww2, bw2, sentence);
    dp_kernel<<<1, 640>>>(out);
}

// round 5
// speedup vs baseline: 2.1364x; 1.1857x over previous
#include <cuda_runtime.h>
#include <math.h>

#define L 40
#define B 16
#define VSZ 10000
#define FDIM 512
#define HDIM 256
#define NPAIR 780                 // triu pairs i<j
#define NROWS ((NPAIR + 1) * B)   // 12496; last 16 rows = init cell (0,0)

#define MT 16                     // rows per CTA == one pair's batch; grid = 781
#define NPR (MT / 2)              // 8 packed row-pairs
#define VT 4                      // vocab columns per thread (consecutive)
#define NGRID (NROWS / MT)        // 781
#define VTILE (256 * VT)          // 1024 vocab per CTA pass
#define NCHUNK ((VSZ + VTILE - 1) / VTILE)   // 10

// ---------------- scratch (device globals; no runtime alloc allowed) ----------
__device__ float g_A1[L * B * HDIM];   // h @ Ww1[:F]
__device__ float g_A2[L * B * HDIM];   // h @ Ww1[F:]
__device__ float g_B1[L * B * HDIM];   // h @ Wt1[:F]
__device__ float g_B2[L * B * HDIM];   // h @ Wt1[F:]
__device__ float g_SH[NPAIR * B];      // log_sigmoid(-t)
__device__ float g_RE[NPAIR * B];      // log_sigmoid(t)
__device__ float g_WLP[NROWS];         // gathered - logsumexp (incl. init rows)
__device__ float g_T[L * L * B];       // DP table

__device__ __forceinline__ void decode_pair(int p, int& i, int& j) {
    int ii = 0;
    while (p >= (L - 1) - ii) { p -= (L - 1) - ii; ++ii; }
    i = ii;
    j = ii + 1 + p;
}

__device__ __forceinline__ int pair_index(int i, int k) {
    return i * (L - 1) - (i * (i - 1)) / 2 + (k - i - 1);
}

__device__ __forceinline__ float logsig(float x) {
    return fminf(x, 0.f) - log1pf(__expf(-fabsf(x)));
}

#define FMA_F32X2(d, a, b, c) \
    asm("fma.rn.f32x2 %0, %1, %2, %3;" : "=l"(d) : "l"(a), "l"(b), "l"(c))
#define SPLAT_F32X2(d, f) \
    asm("mov.b64 %0, {%1, %1};" : "=l"(d) : "f"(f))
#define UNPACK_F32X2(lo, hi, in) \
    asm("mov.b64 {%0, %1}, %2;" : "=f"(lo), "=f"(hi) : "l"(in))

// ---------------- 1) projection GEMMs: C[640,256] = h[640,512] @ Wslice[512,256]
__global__ void proj_kernel(const float* __restrict__ h,
                            const float* __restrict__ Wt1,
                            const float* __restrict__ Ww1) {
    __shared__ float As[16][65];
    __shared__ float Bs[16][65];

    int which = blockIdx.z;
    const float* W = (which < 2) ? Ww1 : Wt1;
    const float* Wbase = W + ((which & 1) ? FDIM * HDIM : 0);
    float* C = (which == 0) ? g_A1 : (which == 1) ? g_A2 : (which == 2) ? g_B1 : g_B2;

    int tx = threadIdx.x;
    int m0 = blockIdx.x * 64;
    int n0 = blockIdx.y * 64;
    int tm = (tx >> 4) * 4;
    int tn = (tx & 15) * 4;

    float acc[4][4];
#pragma unroll
    for (int a = 0; a < 4; a++)
#pragma unroll
        for (int c = 0; c < 4; c++) acc[a][c] = 0.f;

    for (int k0 = 0; k0 < FDIM; k0 += 16) {
#pragma unroll
        for (int l = tx; l < 64 * 16; l += 256) {
            int mm = l >> 4, kk = l & 15;
            As[kk][mm] = h[(m0 + mm) * FDIM + k0 + kk];
        }
#pragma unroll
        for (int l = tx; l < 16 * 64; l += 256) {
            int kk = l >> 6, nn = l & 63;
            Bs[kk][nn] = Wbase[(k0 + kk) * HDIM + n0 + nn];
        }
        __syncthreads();
#pragma unroll
        for (int kk = 0; kk < 16; ++kk) {
            float a0 = As[kk][tm], a1 = As[kk][tm + 1], a2 = As[kk][tm + 2], a3 = As[kk][tm + 3];
            float b0 = Bs[kk][tn], b1 = Bs[kk][tn + 1], b2 = Bs[kk][tn + 2], b3 = Bs[kk][tn + 3];
            acc[0][0] = fmaf(a0, b0, acc[0][0]); acc[0][1] = fmaf(a0, b1, acc[0][1]);
            acc[0][2] = fmaf(a0, b2, acc[0][2]); acc[0][3] = fmaf(a0, b3, acc[0][3]);
            acc[1][0] = fmaf(a1, b0, acc[1][0]); acc[1][1] = fmaf(a1, b1, acc[1][1]);
            acc[1][2] = fmaf(a1, b2, acc[1][2]); acc[1][3] = fmaf(a1, b3, acc[1][3]);
            acc[2][0] = fmaf(a2, b0, acc[2][0]); acc[2][1] = fmaf(a2, b1, acc[2][1]);
            acc[2][2] = fmaf(a2, b2, acc[2][2]); acc[2][3] = fmaf(a2, b3, acc[2][3]);
            acc[3][0] = fmaf(a3, b0, acc[3][0]); acc[3][1] = fmaf(a3, b1, acc[3][1]);
            acc[3][2] = fmaf(a3, b2, acc[3][2]); acc[3][3] = fmaf(a3, b3, acc[3][3]);
        }
        __syncthreads();
    }
#pragma unroll
    for (int a = 0; a < 4; a++)
#pragma unroll
        for (int c = 0; c < 4; c++)
            C[(m0 + tm + a) * HDIM + n0 + tn + c] = acc[a][c];
}

// ---------------- 2) transition MLP per pair -> SH, RE (warp-local)
__global__ void tpair_kernel(const float* __restrict__ bt1,
                             const float* __restrict__ Wt2,
                             const float* __restrict__ bt2) {
    int p = blockIdx.x;
    int tid = threadIdx.x;           // 256
    int wid = tid >> 5, lane = tid & 31;
    int i, j;
    decode_pair(p, i, j);

#pragma unroll
    for (int sub = 0; sub < 2; ++sub) {
        int b = wid * 2 + sub;       // 8 warps x 2 = 16
        const float* r1 = g_B1 + (i * B + b) * HDIM;
        const float* r2 = g_B2 + (j * B + b) * HDIM;
        float acc = 0.f;
#pragma unroll
        for (int hh = lane; hh < HDIM; hh += 32) {
            float hv = tanhf(r1[hh] + r2[hh] + bt1[hh]);
            acc = fmaf(hv, Wt2[hh], acc);
        }
        acc += __shfl_xor_sync(~0u, acc, 16);
        acc += __shfl_xor_sync(~0u, acc, 8);
        acc += __shfl_xor_sync(~0u, acc, 4);
        acc += __shfl_xor_sync(~0u, acc, 2);
        acc += __shfl_xor_sync(~0u, acc, 1);
        if (lane == 0) {
            float t = acc + bt2[0];
            g_SH[p * B + b] = logsig(-t);
            g_RE[p * B + b] = logsig(t);
        }
    }
}

// ---------------- 3) fused: hidden tanh + layer-2 GEMM (f32x2) + sumexp + gather
__global__ __launch_bounds__(256, 2)
void word_kernel(const float* __restrict__ Ww2,
                 const float* __restrict__ bw2,
                 const float* __restrict__ bw1,
                 const int* __restrict__ sentence) {
    // transposed packed hidden tile: hid_p[h][r], r fastest (16 floats per h) = 16 KB
    __shared__ float hid_p[HDIM * MT];
    __shared__ float red_s[MT][8];
    __shared__ float targ_s[MT];
    __shared__ int tgt_s[MT];

    int tid = threadIdx.x;                     // 256
    int p0 = blockIdx.x;                       // pair index (MT == B)
    int row0 = p0 * MT;

    // decode (i,j) for this pair; p0 == NPAIR is the init cell (0,0)
    int pi = 0, pj = 0;
    if (p0 < NPAIR) decode_pair(p0, pi, pj);

    // fused hidden: hid_p[hh*16 + b] = tanh(A1[i,b,hh] + A2[j,b,hh] + bw1[hh])
    for (int idx = tid; idx < MT * HDIM; idx += 256) {
        int r = idx >> 8, hh = idx & 255;      // r = batch b
        float v = tanhf(g_A1[(pi * B + r) * HDIM + hh]
                      + g_A2[(pj * B + r) * HDIM + hh] + bw1[hh]);
        hid_p[hh * MT + r] = v;
    }
    if (tid < MT) {
        int b = tid;
        int t;
        if (p0 == NPAIR) {
            t = sentence[1 * B + b];
        } else {
            int j1 = (pj + 1 < L) ? (pj + 1) : (L - 1);
            t = sentence[j1 * B + b];
        }
        tgt_s[tid] = t;
        targ_s[tid] = 0.f;
    }
    __syncthreads();

    float2 s[NPR];
#pragma unroll
    for (int p = 0; p < NPR; p++) s[p] = make_float2(0.f, 0.f);

    for (int chunk = 0; chunk < NCHUNK; ++chunk) {
        int vc0 = chunk * VTILE + tid * VT;    // 4 consecutive cols; all-or-none valid
        bool valid = (vc0 < VSZ);
        int vca = valid ? vc0 : 0;

        float4 b4 = *(const float4*)(bw2 + vca);
        unsigned long long acc2[VT][NPR];
        {
            unsigned long long i0, i1, i2, i3;
            SPLAT_F32X2(i0, b4.x); SPLAT_F32X2(i1, b4.y);
            SPLAT_F32X2(i2, b4.z); SPLAT_F32X2(i3, b4.w);
#pragma unroll
            for (int p = 0; p < NPR; p++) {
                acc2[0][p] = i0; acc2[1][p] = i1; acc2[2][p] = i2; acc2[3][p] = i3;
            }
        }

        const float4* wp = (const float4*)(Ww2 + vca);   // advance VSZ/4 per k
#pragma unroll 4
        for (int k = 0; k < HDIM; ++k) {
            float4 w4 = __ldg(wp + k * (VSZ / 4));
            unsigned long long ww[VT];
            SPLAT_F32X2(ww[0], w4.x); SPLAT_F32X2(ww[1], w4.y);
            SPLAT_F32X2(ww[2], w4.z); SPLAT_F32X2(ww[3], w4.w);
            const ulonglong2* hp = (const ulonglong2*)(hid_p + k * MT);
#pragma unroll
            for (int q = 0; q < NPR / 2; ++q) {          // 4 x ld.shared.v4 (broadcast)
                ulonglong2 hh = hp[q];
#pragma unroll
                for (int u = 0; u < VT; ++u) {
                    FMA_F32X2(acc2[u][2 * q + 0], hh.x, ww[u], acc2[u][2 * q + 0]);
                    FMA_F32X2(acc2[u][2 * q + 1], hh.y, ww[u], acc2[u][2 * q + 1]);
                }
            }
        }

        if (valid) {
#pragma unroll
            for (int u = 0; u < VT; ++u) {
                int v = vc0 + u;
#pragma unroll
                for (int p = 0; p < NPR; p++) {
                    float alo, ahi;
                    UNPACK_F32X2(alo, ahi, acc2[u][p]);
                    s[p].x += __expf(alo);
                    s[p].y += __expf(ahi);
                    if (v == tgt_s[2 * p + 0]) targ_s[2 * p + 0] = alo;
                    if (v == tgt_s[2 * p + 1]) targ_s[2 * p + 1] = ahi;
                }
            }
        }
    }

    int lane = tid & 31, wid = tid >> 5;
#pragma unroll
    for (int p = 0; p < NPR; p++) {
#pragma unroll
        for (int half = 0; half < 2; ++half) {
            float x = half ? s[p].y : s[p].x;
            x += __shfl_xor_sync(~0u, x, 16);
            x += __shfl_xor_sync(~0u, x, 8);
            x += __shfl_xor_sync(~0u, x, 4);
            x += __shfl_xor_sync(~0u, x, 2);
            x += __shfl_xor_sync(~0u, x, 1);
            if (lane == 0) red_s[2 * p + half][wid] = x;
        }
    }
    __syncthreads();
    if (tid < MT) {
        float tot = 0.f;
#pragma unroll
        for (int w = 0; w < 8; ++w) tot += red_s[tid][w];
        g_WLP[row0 + tid] = targ_s[tid] - logf(tot);
    }
}

// ---------------- 4) CKY DP, single persistent CTA
__global__ void dp_kernel(float* __restrict__ out) {
    int tid = threadIdx.x;       // 640 = 40*16
    int b = tid & 15, i = tid >> 4;

    if (i == 0) {
        g_T[(0 * L + 1) * B + b] = g_WLP[NPAIR * B + b];
    } else if (i >= 1 && i <= 38) {
        g_T[(i * L + (i + 1)) * B + b] = 0.f;
    }
    __syncthreads();

    for (int gap = 2; gap <= L - 1; ++gap) {
        int n_i = L - gap;
        float result = 0.f;
        int j = i + gap;
        if (i < n_i) {
            float m = -1e30f;
            for (int k = i + 1; k < j; ++k) {
                int pik = pair_index(i, k);
                int pkj = pair_index(k, j);
                float sc = g_T[(i * L + k) * B + b] + g_T[(k * L + j) * B + b]
                         + g_SH[pik * B + b] + g_WLP[pik * B + b]
                         + g_RE[pkj * B + b];
                m = fmaxf(m, sc);
            }
            float ssum = 0.f;
            for (int k = i + 1; k < j; ++k) {
                int pik = pair_index(i, k);
                int pkj = pair_index(k, j);
                float sc = g_T[(i * L + k) * B + b] + g_T[(k * L + j) * B + b]
                         + g_SH[pik * B + b] + g_WLP[pik * B + b]
                         + g_RE[pkj * B + b];
                ssum += __expf(sc - m);
            }
            result = m + logf(ssum);
        }
        if (i < n_i) g_T[(i * L + j) * B + b] = result;
        __syncthreads();
    }

    if (tid < B) out[tid] = g_T[(0 * L + (L - 1)) * B + tid];
}

// ---------------- launcher ----------------
extern "C" void kernel_launch(void* const* d_in, const int* in_sizes, int n_in,
                              void* d_out, int out_size) {
    const float* h        = (const float*)d_in[0];
    const int*   sentence = (const int*)d_in[1];
    const float* Wt1      = (const float*)d_in[2];
    const float* bt1      = (const float*)d_in[3];
    const float* Wt2      = (const float*)d_in[4];
    const float* bt2      = (const float*)d_in[5];
    const float* Ww1      = (const float*)d_in[6];
    const float* bw1      = (const float*)d_in[7];
    const float* Ww2      = (const float*)d_in[8];
    const float* bw2      = (const float*)d_in[9];
    float* out = (float*)d_out;

    proj_kernel<<<dim3(10, 4, 4), 256>>>(h, Wt1, Ww1);
    tpair_kernel<<<NPAIR, 256>>>(bt1, Wt2, bt2);
    word_kernel<<<NGRID, 256>>>(Ww2, bw2, bw1, sentence);
    dp_kernel<<<1, 640>>>(out);
}

// round 6
// speedup vs baseline: 2.2616x; 1.0586x over previous
#include <cuda_runtime.h>
#include <math.h>

#define L 40
#define B 16
#define VSZ 10000
#define FDIM 512
#define HDIM 256
#define NPAIR 780                 // triu pairs i<j
#define NROWS ((NPAIR + 1) * B)   // 12496; last 16 rows = init cell (0,0)

#define MT 16                     // rows per CTA == one pair's batch; grid = 781
#define NPR (MT / 2)              // 8 packed row-pairs
#define VT 4                      // vocab columns per thread (consecutive)
#define NGRID (NROWS / MT)        // 781
#define VTILE (256 * VT)          // 1024 vocab per CTA pass
#define NCHUNK ((VSZ + VTILE - 1) / VTILE)   // 10

// dp smem: T + SHW + RE
#define DP_SMEM_BYTES ((L * L * B + 2 * NPAIR * B) * 4)   // 202,240 B

// ---------------- scratch (device globals; no runtime alloc allowed) ----------
__device__ float g_A1[L * B * HDIM];   // h @ Ww1[:F]
__device__ float g_A2[L * B * HDIM];   // h @ Ww1[F:]
__device__ float g_B1[L * B * HDIM];   // h @ Wt1[:F]
__device__ float g_B2[L * B * HDIM];   // h @ Wt1[F:]
__device__ float g_SH[NPAIR * B];      // log_sigmoid(-t)
__device__ float g_RE[NPAIR * B];      // log_sigmoid(t)
__device__ float g_WLP[NROWS];         // gathered - logsumexp (incl. init rows)

__device__ __forceinline__ void decode_pair(int p, int& i, int& j) {
    int ii = 0;
    while (p >= (L - 1) - ii) { p -= (L - 1) - ii; ++ii; }
    i = ii;
    j = ii + 1 + p;
}

__device__ __forceinline__ int pair_index(int i, int k) {
    return i * (L - 1) - (i * (i - 1)) / 2 + (k - i - 1);
}

__device__ __forceinline__ float logsig(float x) {
    return fminf(x, 0.f) - log1pf(__expf(-fabsf(x)));
}

#define FMA_F32X2(d, a, b, c) \
    asm("fma.rn.f32x2 %0, %1, %2, %3;" : "=l"(d) : "l"(a), "l"(b), "l"(c))
#define SPLAT_F32X2(d, f) \
    asm("mov.b64 %0, {%1, %1};" : "=l"(d) : "f"(f))
#define UNPACK_F32X2(lo, hi, in) \
    asm("mov.b64 {%0, %1}, %2;" : "=f"(lo), "=f"(hi) : "l"(in))

// ---------------- 1) projection GEMMs: C[640,256] = h[640,512] @ Wslice[512,256]
__global__ void proj_kernel(const float* __restrict__ h,
                            const float* __restrict__ Wt1,
                            const float* __restrict__ Ww1) {
    __shared__ float As[16][65];
    __shared__ float Bs[16][65];

    int which = blockIdx.z;
    const float* W = (which < 2) ? Ww1 : Wt1;
    const float* Wbase = W + ((which & 1) ? FDIM * HDIM : 0);
    float* C = (which == 0) ? g_A1 : (which == 1) ? g_A2 : (which == 2) ? g_B1 : g_B2;

    int tx = threadIdx.x;
    int m0 = blockIdx.x * 64;
    int n0 = blockIdx.y * 64;
    int tm = (tx >> 4) * 4;
    int tn = (tx & 15) * 4;

    float acc[4][4];
#pragma unroll
    for (int a = 0; a < 4; a++)
#pragma unroll
        for (int c = 0; c < 4; c++) acc[a][c] = 0.f;

    for (int k0 = 0; k0 < FDIM; k0 += 16) {
#pragma unroll
        for (int l = tx; l < 64 * 16; l += 256) {
            int mm = l >> 4, kk = l & 15;
            As[kk][mm] = h[(m0 + mm) * FDIM + k0 + kk];
        }
#pragma unroll
        for (int l = tx; l < 16 * 64; l += 256) {
            int kk = l >> 6, nn = l & 63;
            Bs[kk][nn] = Wbase[(k0 + kk) * HDIM + n0 + nn];
        }
        __syncthreads();
#pragma unroll
        for (int kk = 0; kk < 16; ++kk) {
            float a0 = As[kk][tm], a1 = As[kk][tm + 1], a2 = As[kk][tm + 2], a3 = As[kk][tm + 3];
            float b0 = Bs[kk][tn], b1 = Bs[kk][tn + 1], b2 = Bs[kk][tn + 2], b3 = Bs[kk][tn + 3];
            acc[0][0] = fmaf(a0, b0, acc[0][0]); acc[0][1] = fmaf(a0, b1, acc[0][1]);
            acc[0][2] = fmaf(a0, b2, acc[0][2]); acc[0][3] = fmaf(a0, b3, acc[0][3]);
            acc[1][0] = fmaf(a1, b0, acc[1][0]); acc[1][1] = fmaf(a1, b1, acc[1][1]);
            acc[1][2] = fmaf(a1, b2, acc[1][2]); acc[1][3] = fmaf(a1, b3, acc[1][3]);
            acc[2][0] = fmaf(a2, b0, acc[2][0]); acc[2][1] = fmaf(a2, b1, acc[2][1]);
            acc[2][2] = fmaf(a2, b2, acc[2][2]); acc[2][3] = fmaf(a2, b3, acc[2][3]);
            acc[3][0] = fmaf(a3, b0, acc[3][0]); acc[3][1] = fmaf(a3, b1, acc[3][1]);
            acc[3][2] = fmaf(a3, b2, acc[3][2]); acc[3][3] = fmaf(a3, b3, acc[3][3]);
        }
        __syncthreads();
    }
#pragma unroll
    for (int a = 0; a < 4; a++)
#pragma unroll
        for (int c = 0; c < 4; c++)
            C[(m0 + tm + a) * HDIM + n0 + tn + c] = acc[a][c];
}

// ---------------- 2) transition MLP per pair -> SH, RE (warp-local)
__global__ void tpair_kernel(const float* __restrict__ bt1,
                             const float* __restrict__ Wt2,
                             const float* __restrict__ bt2) {
    int p = blockIdx.x;
    int tid = threadIdx.x;           // 256
    int wid = tid >> 5, lane = tid & 31;
    int i, j;
    decode_pair(p, i, j);

#pragma unroll
    for (int sub = 0; sub < 2; ++sub) {
        int b = wid * 2 + sub;       // 8 warps x 2 = 16
        const float* r1 = g_B1 + (i * B + b) * HDIM;
        const float* r2 = g_B2 + (j * B + b) * HDIM;
        float acc = 0.f;
#pragma unroll
        for (int hh = lane; hh < HDIM; hh += 32) {
            float hv = tanhf(r1[hh] + r2[hh] + bt1[hh]);
            acc = fmaf(hv, Wt2[hh], acc);
        }
        acc += __shfl_xor_sync(~0u, acc, 16);
        acc += __shfl_xor_sync(~0u, acc, 8);
        acc += __shfl_xor_sync(~0u, acc, 4);
        acc += __shfl_xor_sync(~0u, acc, 2);
        acc += __shfl_xor_sync(~0u, acc, 1);
        if (lane == 0) {
            float t = acc + bt2[0];
            g_SH[p * B + b] = logsig(-t);
            g_RE[p * B + b] = logsig(t);
        }
    }
}

// ---------------- 3) fused: hidden tanh + layer-2 GEMM (f32x2) + sumexp + gather
__global__ __launch_bounds__(256, 2)
void word_kernel(const float* __restrict__ Ww2,
                 const float* __restrict__ bw2,
                 const float* __restrict__ bw1,
                 const int* __restrict__ sentence) {
    __shared__ float hid_p[HDIM * MT];     // 16 KB, transposed: hid_p[h][b]
    __shared__ float red_s[MT][8];
    __shared__ float targ_s[MT];
    __shared__ int tgt_s[MT];

    int tid = threadIdx.x;                 // 256
    int p0 = blockIdx.x;                   // pair index (MT == B)
    int row0 = p0 * MT;

    int pi = 0, pj = 0;
    if (p0 < NPAIR) decode_pair(p0, pi, pj);

    for (int idx = tid; idx < MT * HDIM; idx += 256) {
        int r = idx >> 8, hh = idx & 255;
        float v = tanhf(g_A1[(pi * B + r) * HDIM + hh]
                      + g_A2[(pj * B + r) * HDIM + hh] + bw1[hh]);
        hid_p[hh * MT + r] = v;
    }
    if (tid < MT) {
        int b = tid;
        int t;
        if (p0 == NPAIR) {
            t = sentence[1 * B + b];
        } else {
            int j1 = (pj + 1 < L) ? (pj + 1) : (L - 1);
            t = sentence[j1 * B + b];
        }
        tgt_s[tid] = t;
        targ_s[tid] = 0.f;
    }
    __syncthreads();

    float2 s[NPR];
#pragma unroll
    for (int p = 0; p < NPR; p++) s[p] = make_float2(0.f, 0.f);

    for (int chunk = 0; chunk < NCHUNK; ++chunk) {
        int vc0 = chunk * VTILE + tid * VT;    // 4 consecutive cols; all-or-none valid
        bool valid = (vc0 < VSZ);
        int vca = valid ? vc0 : 0;

        float4 b4 = *(const float4*)(bw2 + vca);
        unsigned long long acc2[VT][NPR];
        {
            unsigned long long i0, i1, i2, i3;
            SPLAT_F32X2(i0, b4.x); SPLAT_F32X2(i1, b4.y);
            SPLAT_F32X2(i2, b4.z); SPLAT_F32X2(i3, b4.w);
#pragma unroll
            for (int p = 0; p < NPR; p++) {
                acc2[0][p] = i0; acc2[1][p] = i1; acc2[2][p] = i2; acc2[3][p] = i3;
            }
        }

        const float4* wp = (const float4*)(Ww2 + vca);   // advance VSZ/4 per k
#pragma unroll 8
        for (int k = 0; k < HDIM; ++k) {
            float4 w4 = __ldg(wp + k * (VSZ / 4));
            unsigned long long ww[VT];
            SPLAT_F32X2(ww[0], w4.x); SPLAT_F32X2(ww[1], w4.y);
            SPLAT_F32X2(ww[2], w4.z); SPLAT_F32X2(ww[3], w4.w);
            const ulonglong2* hp = (const ulonglong2*)(hid_p + k * MT);
#pragma unroll
            for (int q = 0; q < NPR / 2; ++q) {          // 4 x ld.shared.v4 (broadcast)
                ulonglong2 hh = hp[q];
#pragma unroll
                for (int u = 0; u < VT; ++u) {
                    FMA_F32X2(acc2[u][2 * q + 0], hh.x, ww[u], acc2[u][2 * q + 0]);
                    FMA_F32X2(acc2[u][2 * q + 1], hh.y, ww[u], acc2[u][2 * q + 1]);
                }
            }
        }

        if (valid) {
#pragma unroll
            for (int u = 0; u < VT; ++u) {
                int v = vc0 + u;
#pragma unroll
                for (int p = 0; p < NPR; p++) {
                    float alo, ahi;
                    UNPACK_F32X2(alo, ahi, acc2[u][p]);
                    s[p].x += __expf(alo);
                    s[p].y += __expf(ahi);
                    if (v == tgt_s[2 * p + 0]) targ_s[2 * p + 0] = alo;
                    if (v == tgt_s[2 * p + 1]) targ_s[2 * p + 1] = ahi;
                }
            }
        }
    }

    int lane = tid & 31, wid = tid >> 5;
#pragma unroll
    for (int p = 0; p < NPR; p++) {
#pragma unroll
        for (int half = 0; half < 2; ++half) {
            float x = half ? s[p].y : s[p].x;
            x += __shfl_xor_sync(~0u, x, 16);
            x += __shfl_xor_sync(~0u, x, 8);
            x += __shfl_xor_sync(~0u, x, 4);
            x += __shfl_xor_sync(~0u, x, 2);
            x += __shfl_xor_sync(~0u, x, 1);
            if (lane == 0) red_s[2 * p + half][wid] = x;
        }
    }
    __syncthreads();
    if (tid < MT) {
        float tot = 0.f;
#pragma unroll
        for (int w = 0; w < 8; ++w) tot += red_s[tid][w];
        g_WLP[row0 + tid] = targ_s[tid] - logf(tot);
    }
}

// ---------------- 4) CKY DP, single CTA, all tables in smem, online LSE
__global__ void dp_kernel(float* __restrict__ out) {
    extern __shared__ float sm[];
    float* T_s   = sm;                         // L*L*B   = 25600
    float* SHW_s = sm + L * L * B;             // NPAIR*B = 12480
    float* RE_s  = SHW_s + NPAIR * B;          // 12480

    int tid = threadIdx.x;                     // 640 = 40*16
    int b = tid & 15, i = tid >> 4;

    // stage SHW = SH + WLP and RE into smem (coalesced)
    for (int idx = tid; idx < NPAIR * B; idx += 640) {
        SHW_s[idx] = g_SH[idx] + g_WLP[idx];
        RE_s[idx]  = g_RE[idx];
    }
    // width-1 init
    if (i == 0) {
        T_s[(0 * L + 1) * B + b] = g_WLP[NPAIR * B + b];
    } else if (i >= 1 && i <= 38) {
        T_s[(i * L + (i + 1)) * B + b] = 0.f;
    }
    __syncthreads();

    for (int gap = 2; gap <= L - 1; ++gap) {
        int n_i = L - gap;
        int j = i + gap;
        if (i < n_i) {
            // single-pass online logsumexp
            float m = -1e30f, ssum = 0.f;
            int pik = pair_index(i, i + 1);            // advances by +1 per k
            for (int k = i + 1; k < j; ++k, ++pik) {
                int pkj = pair_index(k, j);
                float sc = T_s[(i * L + k) * B + b] + T_s[(k * L + j) * B + b]
                         + SHW_s[pik * B + b] + RE_s[pkj * B + b];
                if (sc <= m) {
                    ssum += __expf(sc - m);
                } else {
                    ssum = ssum * __expf(m - sc) + 1.f;
                    m = sc;
                }
            }
            T_s[(i * L + j) * B + b] = m + logf(ssum);
        }
        __syncthreads();
    }

    if (tid < B) out[tid] = T_s[(0 * L + (L - 1)) * B + tid];
}

// ---------------- launcher ----------------
extern "C" void kernel_launch(void* const* d_in, const int* in_sizes, int n_in,
                              void* d_out, int out_size) {
    const float* h        = (const float*)d_in[0];
    const int*   sentence = (const int*)d_in[1];
    const float* Wt1      = (const float*)d_in[2];
    const float* bt1      = (const float*)d_in[3];
    const float* Wt2      = (const float*)d_in[4];
    const float* bt2      = (const float*)d_in[5];
    const float* Ww1      = (const float*)d_in[6];
    const float* bw1      = (const float*)d_in[7];
    const float* Ww2      = (const float*)d_in[8];
    const float* bw2      = (const float*)d_in[9];
    float* out = (float*)d_out;

    static bool attr_set = false;
    if (!attr_set) {
        cudaFuncSetAttribute(dp_kernel, cudaFuncAttributeMaxDynamicSharedMemorySize,
                             DP_SMEM_BYTES);
        attr_set = true;
    }

    proj_kernel<<<dim3(10, 4, 4), 256>>>(h, Wt1, Ww1);
    tpair_kernel<<<NPAIR, 256>>>(bt1, Wt2, bt2);
    word_kernel<<<NGRID, 256>>>(Ww2, bw2, bw1, sentence);
    dp_kernel<<<1, 640, DP_SMEM_BYTES>>>(out);
}

// round 8
// speedup vs baseline: 7.3276x; 3.2400x over previous
#include <cuda_runtime.h>
#include <cuda_bf16.h>
#include <math.h>
#include <stdint.h>

#define L 40
#define B 16
#define VSZ 10000
#define FDIM 512
#define HDIM 256
#define NPAIR 780
#define NROWS ((NPAIR + 1) * B)     // 12496
#define NPADROWS 12544              // 98 * 128
#define MTILE 128
#define NTILE 128
#define NT_N 79                     // ceil(10000/128)
#define NPADN (NT_N * NTILE)        // 10112
#define YS 3                        // N-splits

#define DP_SMEM_BYTES ((L * L * B + 2 * NPAIR * B) * 4)   // 202,240 B

// word MMA smem layout (bytes)
#define PITCH 264                    // halves per row (256 + 8 pad)
#define SM_A 0                       // 128 * 264 * 2 = 67584
#define SM_B 67584                   // 67584
#define SM_BIAS 135168               // 128 f32
#define SM_TGT  135680               // 128 i32
#define SM_RED  136192               // 128*4 f32 = 2048
#define WORD_SMEM (SM_RED + 2048 + 64)

// ---------------- device scratch ----------------
__device__ float g_A1[L * B * HDIM];
__device__ float g_A2[L * B * HDIM];
__device__ float g_B1[L * B * HDIM];
__device__ float g_B2[L * B * HDIM];
__device__ float g_SH[NPAIR * B];
__device__ float g_RE[NPAIR * B];
__device__ float g_WLP[NROWS];
__device__ __nv_bfloat16 g_Hb[NPADROWS * HDIM];   // bf16 hidden (pad rows stay 0)
__device__ __nv_bfloat16 g_Wb[NPADN * HDIM];      // bf16 Ww2 transposed [n][k]
__device__ float g_PS[YS * NPADROWS];             // partial sum-of-exp
__device__ float g_TG[NPADROWS];                  // target logit
__device__ int   g_TGTI[NPADROWS];                // target vocab index per row

__device__ __forceinline__ void decode_pair(int p, int& i, int& j) {
    int ii = 0;
    while (p >= (L - 1) - ii) { p -= (L - 1) - ii; ++ii; }
    i = ii;
    j = ii + 1 + p;
}
__device__ __forceinline__ int pair_index(int i, int k) {
    return i * (L - 1) - (i * (i - 1)) / 2 + (k - i - 1);
}
__device__ __forceinline__ float logsig(float x) {
    return fminf(x, 0.f) - log1pf(__expf(-fabsf(x)));
}
__device__ __forceinline__ uint32_t smem_u32(const void* p) {
    uint32_t a;
    asm("{ .reg .u64 t; cvta.to.shared.u64 t, %1; cvt.u32.u64 %0, t; }" : "=r"(a) : "l"(p));
    return a;
}

#define LDSM_X4(r0, r1, r2, r3, addr)                                         \
    asm volatile("ldmatrix.sync.aligned.m8n8.x4.shared.b16 {%0,%1,%2,%3}, [%4];" \
                 : "=r"(r0), "=r"(r1), "=r"(r2), "=r"(r3) : "r"(addr))

#define MMA_BF16(d, a, b0v, b1v)                                              \
    asm volatile("mma.sync.aligned.m16n8k16.row.col.f32.bf16.bf16.f32 "       \
                 "{%0,%1,%2,%3}, {%4,%5,%6,%7}, {%8,%9}, {%0,%1,%2,%3};"      \
                 : "+f"((d)[0]), "+f"((d)[1]), "+f"((d)[2]), "+f"((d)[3])     \
                 : "r"((a)[0]), "r"((a)[1]), "r"((a)[2]), "r"((a)[3]),        \
                   "r"(b0v), "r"(b1v))

// ---------------- 1) projection GEMMs ----------------
__global__ void proj_kernel(const float* __restrict__ h,
                            const float* __restrict__ Wt1,
                            const float* __restrict__ Ww1) {
    __shared__ float As[16][65];
    __shared__ float Bs[16][65];

    int which = blockIdx.z;
    const float* W = (which < 2) ? Ww1 : Wt1;
    const float* Wbase = W + ((which & 1) ? FDIM * HDIM : 0);
    float* C = (which == 0) ? g_A1 : (which == 1) ? g_A2 : (which == 2) ? g_B1 : g_B2;

    int tx = threadIdx.x;
    int m0 = blockIdx.x * 64;
    int n0 = blockIdx.y * 64;
    int tm = (tx >> 4) * 4;
    int tn = (tx & 15) * 4;

    float acc[4][4];
#pragma unroll
    for (int a = 0; a < 4; a++)
#pragma unroll
        for (int c = 0; c < 4; c++) acc[a][c] = 0.f;

    for (int k0 = 0; k0 < FDIM; k0 += 16) {
#pragma unroll
        for (int l = tx; l < 64 * 16; l += 256) {
            int mm = l >> 4, kk = l & 15;
            As[kk][mm] = h[(m0 + mm) * FDIM + k0 + kk];
        }
#pragma unroll
        for (int l = tx; l < 16 * 64; l += 256) {
            int kk = l >> 6, nn = l & 63;
            Bs[kk][nn] = Wbase[(k0 + kk) * HDIM + n0 + nn];
        }
        __syncthreads();
#pragma unroll
        for (int kk = 0; kk < 16; ++kk) {
            float a0 = As[kk][tm], a1 = As[kk][tm + 1], a2 = As[kk][tm + 2], a3 = As[kk][tm + 3];
            float b0 = Bs[kk][tn], b1 = Bs[kk][tn + 1], b2 = Bs[kk][tn + 2], b3 = Bs[kk][tn + 3];
            acc[0][0] = fmaf(a0, b0, acc[0][0]); acc[0][1] = fmaf(a0, b1, acc[0][1]);
            acc[0][2] = fmaf(a0, b2, acc[0][2]); acc[0][3] = fmaf(a0, b3, acc[0][3]);
            acc[1][0] = fmaf(a1, b0, acc[1][0]); acc[1][1] = fmaf(a1, b1, acc[1][1]);
            acc[1][2] = fmaf(a1, b2, acc[1][2]); acc[1][3] = fmaf(a1, b3, acc[1][3]);
            acc[2][0] = fmaf(a2, b0, acc[2][0]); acc[2][1] = fmaf(a2, b1, acc[2][1]);
            acc[2][2] = fmaf(a2, b2, acc[2][2]); acc[2][3] = fmaf(a2, b3, acc[2][3]);
            acc[3][0] = fmaf(a3, b0, acc[3][0]); acc[3][1] = fmaf(a3, b1, acc[3][1]);
            acc[3][2] = fmaf(a3, b2, acc[3][2]); acc[3][3] = fmaf(a3, b3, acc[3][3]);
        }
        __syncthreads();
    }
#pragma unroll
    for (int a = 0; a < 4; a++)
#pragma unroll
        for (int c = 0; c < 4; c++)
            C[(m0 + tm + a) * HDIM + n0 + tn + c] = acc[a][c];
}

// ---------------- 2) transition MLP ----------------
__global__ void tpair_kernel(const float* __restrict__ bt1,
                             const float* __restrict__ Wt2,
                             const float* __restrict__ bt2) {
    int p = blockIdx.x;
    int tid = threadIdx.x;
    int wid = tid >> 5, lane = tid & 31;
    int i, j;
    decode_pair(p, i, j);

#pragma unroll
    for (int sub = 0; sub < 2; ++sub) {
        int b = wid * 2 + sub;
        const float* r1 = g_B1 + (i * B + b) * HDIM;
        const float* r2 = g_B2 + (j * B + b) * HDIM;
        float acc = 0.f;
#pragma unroll
        for (int hh = lane; hh < HDIM; hh += 32) {
            float hv = tanhf(r1[hh] + r2[hh] + bt1[hh]);
            acc = fmaf(hv, Wt2[hh], acc);
        }
        acc += __shfl_xor_sync(~0u, acc, 16);
        acc += __shfl_xor_sync(~0u, acc, 8);
        acc += __shfl_xor_sync(~0u, acc, 4);
        acc += __shfl_xor_sync(~0u, acc, 2);
        acc += __shfl_xor_sync(~0u, acc, 1);
        if (lane == 0) {
            float t = acc + bt2[0];
            g_SH[p * B + b] = logsig(-t);
            g_RE[p * B + b] = logsig(t);
        }
    }
}

// ---------------- 3a) bf16 hidden + per-row target ----------------
__global__ void hiddenb_kernel(const float* __restrict__ bw1,
                               const int* __restrict__ sentence) {
    int r = blockIdx.x;
    int tid = threadIdx.x;
    int p = r >> 4, b = r & 15;
    int i = 0, j = 0;
    if (p < NPAIR) decode_pair(p, i, j);
    float v = tanhf(g_A1[(i * B + b) * HDIM + tid] + g_A2[(j * B + b) * HDIM + tid] + bw1[tid]);
    g_Hb[r * HDIM + tid] = __float2bfloat16(v);
    if (tid == 0) {
        int t;
        if (p == NPAIR) t = sentence[1 * B + b];
        else {
            int j1 = (j + 1 < L) ? (j + 1) : (L - 1);
            t = sentence[j1 * B + b];
        }
        g_TGTI[r] = t;
    }
}

// ---------------- 3b) transpose+convert Ww2 -> g_Wb[n][k] bf16 ----------------
__global__ void wconv_kernel(const float* __restrict__ Ww2) {
    __shared__ float t[32][33];
    int kt = blockIdx.x, nt = blockIdx.y;
    int tx = threadIdx.x, ty = threadIdx.y;
    int k = kt * 32 + ty, n = nt * 32 + tx;
    t[ty][tx] = (n < VSZ) ? Ww2[k * VSZ + n] : 0.f;
    __syncthreads();
    int n2 = nt * 32 + ty, k2 = kt * 32 + tx;
    g_Wb[n2 * HDIM + k2] = __float2bfloat16(t[tx][ty]);
}

// ---------------- 3c) word GEMM via mma.sync bf16 + fused softmax pieces ------
__global__ __launch_bounds__(256)
void wordmma_kernel(const float* __restrict__ bw2) {
    extern __shared__ char smem[];
    uint32_t sb = smem_u32(smem);
    float* bias_s = (float*)(smem + SM_BIAS);
    int*   tgt_s  = (int*)(smem + SM_TGT);
    float* red_s  = (float*)(smem + SM_RED);

    int tid = threadIdx.x;
    int wid = tid >> 5, lane = tid & 31;
    int tq = lane & 3, gid = lane >> 2;
    int mt = blockIdx.x, ys = blockIdx.y;
    int warp_m = (wid & 1) * 64;
    int warp_n = (wid >> 1) * 32;

    // load A tile (128 x 256 bf16) into smem, pitch 264 halves
    {
        const __nv_bfloat16* hb = g_Hb + (size_t)mt * MTILE * HDIM;
        for (int idx = tid; idx < 128 * 32; idx += 256) {
            int r = idx >> 5, seg = idx & 31;
            uint4 v = *(const uint4*)(hb + r * HDIM + seg * 8);
            *(uint4*)(smem + SM_A + (r * PITCH + seg * 8) * 2) = v;
        }
    }
    if (tid < 128) tgt_s[tid] = g_TGTI[mt * MTILE + tid];

    float rs[4][2];
#pragma unroll
    for (int mi = 0; mi < 4; ++mi) { rs[mi][0] = 0.f; rs[mi][1] = 0.f; }

    int nt0 = (ys * NT_N) / YS, nt1 = ((ys + 1) * NT_N) / YS;

    for (int nt = nt0; nt < nt1; ++nt) {
        int n0 = nt * NTILE;
        __syncthreads();    // previous iter's smem reads done (also orders A stores)
        {
            const __nv_bfloat16* wb = g_Wb + (size_t)n0 * HDIM;
            for (int idx = tid; idx < 128 * 32; idx += 256) {
                int r = idx >> 5, seg = idx & 31;
                uint4 v = *(const uint4*)(wb + r * HDIM + seg * 8);
                *(uint4*)(smem + SM_B + (r * PITCH + seg * 8) * 2) = v;
            }
        }
        if (tid < 128) {
            int col = n0 + tid;
            bias_s[tid] = (col < VSZ) ? bw2[col] : 0.f;
        }
        __syncthreads();

        float d[4][4][4];
#pragma unroll
        for (int mi = 0; mi < 4; ++mi)
#pragma unroll
            for (int ni = 0; ni < 4; ++ni)
#pragma unroll
                for (int r = 0; r < 4; ++r) d[mi][ni][r] = 0.f;

#pragma unroll
        for (int ks = 0; ks < 16; ++ks) {
            int k0 = ks * 16;
            uint32_t a[4][4];
#pragma unroll
            for (int mi = 0; mi < 4; ++mi) {
                uint32_t row = warp_m + mi * 16 + (lane & 15);
                uint32_t col = k0 + ((lane >> 4) << 3);
                uint32_t ad = sb + SM_A + (row * PITCH + col) * 2;
                LDSM_X4(a[mi][0], a[mi][1], a[mi][2], a[mi][3], ad);
            }
#pragma unroll
            for (int nq = 0; nq < 2; ++nq) {
                uint32_t nrow = warp_n + nq * 16 + (lane & 7) + ((lane >> 4) << 3);
                uint32_t col = k0 + (((lane >> 3) & 1) << 3);
                uint32_t bd = sb + SM_B + (nrow * PITCH + col) * 2;
                uint32_t bfr[4];
                LDSM_X4(bfr[0], bfr[1], bfr[2], bfr[3], bd);
#pragma unroll
                for (int mi = 0; mi < 4; ++mi) {
                    MMA_BF16(d[mi][nq * 2 + 0], a[mi], bfr[0], bfr[1]);
                    MMA_BF16(d[mi][nq * 2 + 1], a[mi], bfr[2], bfr[3]);
                }
            }
        }

        // epilogue: bias + exp-sum + target gather
#pragma unroll
        for (int mi = 0; mi < 4; ++mi) {
            int r0 = warp_m + mi * 16 + gid;
            int r1 = r0 + 8;
            int t0 = tgt_s[r0], t1 = tgt_s[r1];
            int grow0 = mt * MTILE + r0, grow1 = mt * MTILE + r1;
            float acc0 = 0.f, acc1 = 0.f;
#pragma unroll
            for (int ni = 0; ni < 4; ++ni) {
                int cl = warp_n + ni * 8 + tq * 2;
                int colb = n0 + cl;
                float bia0 = bias_s[cl], bia1 = bias_s[cl + 1];
                float v0 = d[mi][ni][0] + bia0;
                float v1 = d[mi][ni][1] + bia1;
                float v2 = d[mi][ni][2] + bia0;
                float v3 = d[mi][ni][3] + bia1;
                if (colb < VSZ) {
                    acc0 += __expf(v0);
                    acc1 += __expf(v2);
                    if (colb == t0) g_TG[grow0] = v0;
                    if (colb == t1) g_TG[grow1] = v2;
                }
                if (colb + 1 < VSZ) {
                    acc0 += __expf(v1);
                    acc1 += __expf(v3);
                    if (colb + 1 == t0) g_TG[grow0] = v1;
                    if (colb + 1 == t1) g_TG[grow1] = v3;
                }
            }
            rs[mi][0] += acc0;
            rs[mi][1] += acc1;
        }
    }

    // reduce rowsum across the 4 lanes of each row group
#pragma unroll
    for (int mi = 0; mi < 4; ++mi) {
#pragma unroll
        for (int hh = 0; hh < 2; ++hh) {
            float x = rs[mi][hh];
            x += __shfl_xor_sync(~0u, x, 1);
            x += __shfl_xor_sync(~0u, x, 2);
            if (tq == 0) {
                int row_l = warp_m + mi * 16 + gid + hh * 8;
                red_s[row_l * 4 + (wid >> 1)] = x;
            }
        }
    }
    __syncthreads();
    if (tid < 128) {
        float s = red_s[tid * 4 + 0] + red_s[tid * 4 + 1]
                + red_s[tid * 4 + 2] + red_s[tid * 4 + 3];
        g_PS[ys * NPADROWS + mt * MTILE + tid] = s;
    }
}

// ---------------- 3d) fixup: WLP = target - log(sum of partials) ------------
__global__ void fixup_kernel() {
    int r = blockIdx.x * 256 + threadIdx.x;
    if (r < NROWS) {
        float s = g_PS[r] + g_PS[NPADROWS + r] + g_PS[2 * NPADROWS + r];
        g_WLP[r] = g_TG[r] - logf(s);
    }
}

// ---------------- 4) CKY DP (smem, branch-free online LSE) -------------------
__global__ void dp_kernel(float* __restrict__ out) {
    extern __shared__ float sm[];
    float* T_s   = sm;
    float* SHW_s = sm + L * L * B;
    float* RE_s  = SHW_s + NPAIR * B;

    int tid = threadIdx.x;                 // 640
    int b = tid & 15, i = tid >> 4;

    for (int idx = tid; idx < NPAIR * B; idx += 640) {
        SHW_s[idx] = g_SH[idx] + g_WLP[idx];
        RE_s[idx]  = g_RE[idx];
    }
    if (i == 0) {
        T_s[(0 * L + 1) * B + b] = g_WLP[NPAIR * B + b];
    } else if (i >= 1 && i <= 38) {
        T_s[(i * L + (i + 1)) * B + b] = 0.f;
    }
    __syncthreads();

    for (int gap = 2; gap <= L - 1; ++gap) {
        int n_i = L - gap;
        int j = i + gap;
        if (i < n_i) {
            float m = -1e30f, ssum = 0.f;
            int pik = pair_index(i, i + 1);
#pragma unroll 2
            for (int k = i + 1; k < j; ++k, ++pik) {
                int pkj = pair_index(k, j);
                float sc = T_s[(i * L + k) * B + b] + T_s[(k * L + j) * B + b]
                         + SHW_s[pik * B + b] + RE_s[pkj * B + b];
                float mn = fmaxf(m, sc);
                ssum = fmaf(ssum, __expf(m - mn), __expf(sc - mn));
                m = mn;
            }
            T_s[(i * L + j) * B + b] = m + logf(ssum);
        }
        __syncthreads();
    }

    if (tid < B) out[tid] = T_s[(0 * L + (L - 1)) * B + tid];
}

// ---------------- launcher ----------------
extern "C" void kernel_launch(void* const* d_in, const int* in_sizes, int n_in,
                              void* d_out, int out_size) {
    const float* h        = (const float*)d_in[0];
    const int*   sentence = (const int*)d_in[1];
    const float* Wt1      = (const float*)d_in[2];
    const float* bt1      = (const float*)d_in[3];
    const float* Wt2      = (const float*)d_in[4];
    const float* bt2      = (const float*)d_in[5];
    const float* Ww1      = (const float*)d_in[6];
    const float* bw1      = (const float*)d_in[7];
    const float* Ww2      = (const float*)d_in[8];
    const float* bw2      = (const float*)d_in[9];
    float* out = (float*)d_out;

    static bool attr_set = false;
    if (!attr_set) {
        cudaFuncSetAttribute(dp_kernel, cudaFuncAttributeMaxDynamicSharedMemorySize,
                             DP_SMEM_BYTES);
        cudaFuncSetAttribute(wordmma_kernel, cudaFuncAttributeMaxDynamicSharedMemorySize,
                             WORD_SMEM);
        attr_set = true;
    }

    proj_kernel<<<dim3(10, 4, 4), 256>>>(h, Wt1, Ww1);
    tpair_kernel<<<NPAIR, 256>>>(bt1, Wt2, bt2);
    hiddenb_kernel<<<NROWS, 256>>>(bw1, sentence);
    wconv_kernel<<<dim3(HDIM / 32, NPADN / 32), dim3(32, 32)>>>(Ww2);
    wordmma_kernel<<<dim3(NPADROWS / MTILE, YS), 256, WORD_SMEM>>>(bw2);
    fixup_kernel<<<(NROWS + 255) / 256, 256>>>();
    dp_kernel<<<1, 640, DP_SMEM_BYTES>>>(out);
}

// round 9
// speedup vs baseline: 8.9090x; 1.2158x over previous
#include <cuda_runtime.h>
#include <cuda_bf16.h>
#include <math.h>
#include <stdint.h>

#define L 40
#define B 16
#define VSZ 10000
#define FDIM 512
#define HDIM 256
#define NPAIR 780
#define NROWS ((NPAIR + 1) * B)     // 12496
#define NPADROWS 12544              // 49 * 256
#define MTILE 256
#define NTILE 128
#define NMT (NPADROWS / MTILE)      // 49
#define NT_N 79                     // ceil(10000/128)
#define YS 3                        // N-splits

#define DP_SMEM_BYTES ((L * L * B + 2 * NPAIR * B) * 4)   // 202,240 B

// word MMA smem layout (bytes)
#define PITCH 264                    // halves per row (256 + 8 pad)
#define SM_A 0                       // 256 * 264 * 2 = 135168
#define SM_B 135168                  // 128 * 264 * 2 = 67584
#define SM_BIAS 202752               // 128 f32
#define SM_TGT  203264               // 256 i32
#define SM_RED  204288               // 256*4 f32 = 4096
#define WORD_SMEM (SM_RED + 4096)    // 208384

// ---------------- device scratch ----------------
__device__ float g_A1[L * B * HDIM];
__device__ float g_A2[L * B * HDIM];
__device__ float g_B1[L * B * HDIM];
__device__ float g_B2[L * B * HDIM];
__device__ float g_SH[NPAIR * B];
__device__ float g_RE[NPAIR * B];
__device__ float g_WLP[NROWS];
__device__ __nv_bfloat16 g_Hb[NPADROWS * HDIM];   // bf16 hidden (pad rows stay 0)
__device__ __nv_bfloat16 g_Wb[NT_N * NTILE * HDIM];  // bf16 Ww2 transposed [n][k]
__device__ float g_PS[YS * NPADROWS];             // partial sum-of-exp
__device__ float g_TG[NPADROWS];                  // target logit
__device__ int   g_TGTI[NPADROWS];                // target vocab index per row

__device__ __forceinline__ void decode_pair(int p, int& i, int& j) {
    int ii = 0;
    while (p >= (L - 1) - ii) { p -= (L - 1) - ii; ++ii; }
    i = ii;
    j = ii + 1 + p;
}
__device__ __forceinline__ int pair_index(int i, int k) {
    return i * (L - 1) - (i * (i - 1)) / 2 + (k - i - 1);
}
__device__ __forceinline__ float logsig(float x) {
    return fminf(x, 0.f) - log1pf(__expf(-fabsf(x)));
}
__device__ __forceinline__ uint32_t smem_u32(const void* p) {
    uint32_t a;
    asm("{ .reg .u64 t; cvta.to.shared.u64 t, %1; cvt.u32.u64 %0, t; }" : "=r"(a) : "l"(p));
    return a;
}

#define LDSM_X4(r0, r1, r2, r3, addr)                                         \
    asm volatile("ldmatrix.sync.aligned.m8n8.x4.shared.b16 {%0,%1,%2,%3}, [%4];" \
                 : "=r"(r0), "=r"(r1), "=r"(r2), "=r"(r3) : "r"(addr))

#define MMA_BF16(d, a, b0v, b1v)                                              \
    asm volatile("mma.sync.aligned.m16n8k16.row.col.f32.bf16.bf16.f32 "       \
                 "{%0,%1,%2,%3}, {%4,%5,%6,%7}, {%8,%9}, {%0,%1,%2,%3};"      \
                 : "+f"((d)[0]), "+f"((d)[1]), "+f"((d)[2]), "+f"((d)[3])     \
                 : "r"((a)[0]), "r"((a)[1]), "r"((a)[2]), "r"((a)[3]),        \
                   "r"(b0v), "r"(b1v))

// ---------------- 1) projection GEMMs ----------------
__global__ void proj_kernel(const float* __restrict__ h,
                            const float* __restrict__ Wt1,
                            const float* __restrict__ Ww1) {
    __shared__ float As[16][65];
    __shared__ float Bs[16][65];

    int which = blockIdx.z;
    const float* W = (which < 2) ? Ww1 : Wt1;
    const float* Wbase = W + ((which & 1) ? FDIM * HDIM : 0);
    float* C = (which == 0) ? g_A1 : (which == 1) ? g_A2 : (which == 2) ? g_B1 : g_B2;

    int tx = threadIdx.x;
    int m0 = blockIdx.x * 64;
    int n0 = blockIdx.y * 64;
    int tm = (tx >> 4) * 4;
    int tn = (tx & 15) * 4;

    float acc[4][4];
#pragma unroll
    for (int a = 0; a < 4; a++)
#pragma unroll
        for (int c = 0; c < 4; c++) acc[a][c] = 0.f;

    for (int k0 = 0; k0 < FDIM; k0 += 16) {
#pragma unroll
        for (int l = tx; l < 64 * 16; l += 256) {
            int mm = l >> 4, kk = l & 15;
            As[kk][mm] = h[(m0 + mm) * FDIM + k0 + kk];
        }
#pragma unroll
        for (int l = tx; l < 16 * 64; l += 256) {
            int kk = l >> 6, nn = l & 63;
            Bs[kk][nn] = Wbase[(k0 + kk) * HDIM + n0 + nn];
        }
        __syncthreads();
#pragma unroll
        for (int kk = 0; kk < 16; ++kk) {
            float a0 = As[kk][tm], a1 = As[kk][tm + 1], a2 = As[kk][tm + 2], a3 = As[kk][tm + 3];
            float b0 = Bs[kk][tn], b1 = Bs[kk][tn + 1], b2 = Bs[kk][tn + 2], b3 = Bs[kk][tn + 3];
            acc[0][0] = fmaf(a0, b0, acc[0][0]); acc[0][1] = fmaf(a0, b1, acc[0][1]);
            acc[0][2] = fmaf(a0, b2, acc[0][2]); acc[0][3] = fmaf(a0, b3, acc[0][3]);
            acc[1][0] = fmaf(a1, b0, acc[1][0]); acc[1][1] = fmaf(a1, b1, acc[1][1]);
            acc[1][2] = fmaf(a1, b2, acc[1][2]); acc[1][3] = fmaf(a1, b3, acc[1][3]);
            acc[2][0] = fmaf(a2, b0, acc[2][0]); acc[2][1] = fmaf(a2, b1, acc[2][1]);
            acc[2][2] = fmaf(a2, b2, acc[2][2]); acc[2][3] = fmaf(a2, b3, acc[2][3]);
            acc[3][0] = fmaf(a3, b0, acc[3][0]); acc[3][1] = fmaf(a3, b1, acc[3][1]);
            acc[3][2] = fmaf(a3, b2, acc[3][2]); acc[3][3] = fmaf(a3, b3, acc[3][3]);
        }
        __syncthreads();
    }
#pragma unroll
    for (int a = 0; a < 4; a++)
#pragma unroll
        for (int c = 0; c < 4; c++)
            C[(m0 + tm + a) * HDIM + n0 + tn + c] = acc[a][c];
}

// ---------------- 2) transition MLP ----------------
__global__ void tpair_kernel(const float* __restrict__ bt1,
                             const float* __restrict__ Wt2,
                             const float* __restrict__ bt2) {
    int p = blockIdx.x;
    int tid = threadIdx.x;
    int wid = tid >> 5, lane = tid & 31;
    int i, j;
    decode_pair(p, i, j);

#pragma unroll
    for (int sub = 0; sub < 2; ++sub) {
        int b = wid * 2 + sub;
        const float* r1 = g_B1 + (i * B + b) * HDIM;
        const float* r2 = g_B2 + (j * B + b) * HDIM;
        float acc = 0.f;
#pragma unroll
        for (int hh = lane; hh < HDIM; hh += 32) {
            float hv = tanhf(r1[hh] + r2[hh] + bt1[hh]);
            acc = fmaf(hv, Wt2[hh], acc);
        }
        acc += __shfl_xor_sync(~0u, acc, 16);
        acc += __shfl_xor_sync(~0u, acc, 8);
        acc += __shfl_xor_sync(~0u, acc, 4);
        acc += __shfl_xor_sync(~0u, acc, 2);
        acc += __shfl_xor_sync(~0u, acc, 1);
        if (lane == 0) {
            float t = acc + bt2[0];
            g_SH[p * B + b] = logsig(-t);
            g_RE[p * B + b] = logsig(t);
        }
    }
}

// ---------------- 3a) bf16 hidden + per-row target ----------------
__global__ void hiddenb_kernel(const float* __restrict__ bw1,
                               const int* __restrict__ sentence) {
    int r = blockIdx.x;
    int tid = threadIdx.x;
    int p = r >> 4, b = r & 15;
    int i = 0, j = 0;
    if (p < NPAIR) decode_pair(p, i, j);
    float v = tanhf(g_A1[(i * B + b) * HDIM + tid] + g_A2[(j * B + b) * HDIM + tid] + bw1[tid]);
    g_Hb[r * HDIM + tid] = __float2bfloat16(v);
    if (tid == 0) {
        int t;
        if (p == NPAIR) t = sentence[1 * B + b];
        else {
            int j1 = (j + 1 < L) ? (j + 1) : (L - 1);
            t = sentence[j1 * B + b];
        }
        g_TGTI[r] = t;
    }
}

// ---------------- 3b) transpose+convert Ww2 -> g_Wb[n][k] bf16 ----------------
__global__ void wconv_kernel(const float* __restrict__ Ww2) {
    __shared__ float t[32][33];
    int kt = blockIdx.x, nt = blockIdx.y;
    int tx = threadIdx.x, ty = threadIdx.y;
    int k = kt * 32 + ty, n = nt * 32 + tx;
    t[ty][tx] = (n < VSZ) ? Ww2[k * VSZ + n] : 0.f;
    __syncthreads();
    int n2 = nt * 32 + ty, k2 = kt * 32 + tx;
    g_Wb[n2 * HDIM + k2] = __float2bfloat16(t[tx][ty]);
}

// ---------------- 3c) word GEMM via mma.sync bf16 + fused softmax pieces ------
__global__ __launch_bounds__(512)
void wordmma_kernel(const float* __restrict__ bw2) {
    extern __shared__ char smem[];
    uint32_t sb = smem_u32(smem);
    float* bias_s = (float*)(smem + SM_BIAS);
    int*   tgt_s  = (int*)(smem + SM_TGT);
    float* red_s  = (float*)(smem + SM_RED);

    int tid = threadIdx.x;                 // 512
    int wid = tid >> 5, lane = tid & 31;
    int tq = lane & 3, gid = lane >> 2;
    int mt = blockIdx.x, ys = blockIdx.y;
    int warp_m = (wid & 3) * 64;           // 4 m-groups
    int warp_n = (wid >> 2) * 32;          // 4 n-groups

    // load A tile (256 x 256 bf16) into smem, pitch 264 halves
    {
        const __nv_bfloat16* hb = g_Hb + (size_t)mt * MTILE * HDIM;
        for (int idx = tid; idx < 256 * 32; idx += 512) {
            int r = idx >> 5, seg = idx & 31;
            uint4 v = *(const uint4*)(hb + r * HDIM + seg * 8);
            *(uint4*)(smem + SM_A + (r * PITCH + seg * 8) * 2) = v;
        }
    }
    if (tid < 256) tgt_s[tid] = g_TGTI[mt * MTILE + tid];

    float rs[4][2];
#pragma unroll
    for (int mi = 0; mi < 4; ++mi) { rs[mi][0] = 0.f; rs[mi][1] = 0.f; }

    int nt0 = (ys * NT_N) / YS, nt1 = ((ys + 1) * NT_N) / YS;

    for (int nt = nt0; nt < nt1; ++nt) {
        int n0 = nt * NTILE;
        __syncthreads();    // previous iter's smem reads done (also orders A stores)
        {
            const __nv_bfloat16* wb = g_Wb + (size_t)n0 * HDIM;
            for (int idx = tid; idx < 128 * 32; idx += 512) {
                int r = idx >> 5, seg = idx & 31;
                uint4 v = *(const uint4*)(wb + r * HDIM + seg * 8);
                *(uint4*)(smem + SM_B + (r * PITCH + seg * 8) * 2) = v;
            }
        }
        if (tid < 128) {
            int col = n0 + tid;
            bias_s[tid] = (col < VSZ) ? bw2[col] : 0.f;
        }
        __syncthreads();

        float d[4][4][4];
#pragma unroll
        for (int mi = 0; mi < 4; ++mi)
#pragma unroll
            for (int ni = 0; ni < 4; ++ni)
#pragma unroll
                for (int r = 0; r < 4; ++r) d[mi][ni][r] = 0.f;

#pragma unroll
        for (int ks = 0; ks < 16; ++ks) {
            int k0 = ks * 16;
            uint32_t a[4][4];
#pragma unroll
            for (int mi = 0; mi < 4; ++mi) {
                uint32_t row = warp_m + mi * 16 + (lane & 15);
                uint32_t col = k0 + ((lane >> 4) << 3);
                uint32_t ad = sb + SM_A + (row * PITCH + col) * 2;
                LDSM_X4(a[mi][0], a[mi][1], a[mi][2], a[mi][3], ad);
            }
#pragma unroll
            for (int nq = 0; nq < 2; ++nq) {
                uint32_t nrow = warp_n + nq * 16 + (lane & 7) + ((lane >> 4) << 3);
                uint32_t col = k0 + (((lane >> 3) & 1) << 3);
                uint32_t bd = sb + SM_B + (nrow * PITCH + col) * 2;
                uint32_t bfr[4];
                LDSM_X4(bfr[0], bfr[1], bfr[2], bfr[3], bd);
#pragma unroll
                for (int mi = 0; mi < 4; ++mi) {
                    MMA_BF16(d[mi][nq * 2 + 0], a[mi], bfr[0], bfr[1]);
                    MMA_BF16(d[mi][nq * 2 + 1], a[mi], bfr[2], bfr[3]);
                }
            }
        }

        // epilogue: bias + exp-sum + target gather
#pragma unroll
        for (int mi = 0; mi < 4; ++mi) {
            int r0 = warp_m + mi * 16 + gid;
            int r1 = r0 + 8;
            int t0 = tgt_s[r0], t1 = tgt_s[r1];
            int grow0 = mt * MTILE + r0, grow1 = mt * MTILE + r1;
            float acc0 = 0.f, acc1 = 0.f;
#pragma unroll
            for (int ni = 0; ni < 4; ++ni) {
                int cl = warp_n + ni * 8 + tq * 2;
                int colb = n0 + cl;
                float bia0 = bias_s[cl], bia1 = bias_s[cl + 1];
                float v0 = d[mi][ni][0] + bia0;
                float v1 = d[mi][ni][1] + bia1;
                float v2 = d[mi][ni][2] + bia0;
                float v3 = d[mi][ni][3] + bia1;
                if (colb < VSZ) {
                    acc0 += __expf(v0);
                    acc1 += __expf(v2);
                    if (colb == t0) g_TG[grow0] = v0;
                    if (colb == t1) g_TG[grow1] = v2;
                }
                if (colb + 1 < VSZ) {
                    acc0 += __expf(v1);
                    acc1 += __expf(v3);
                    if (colb + 1 == t0) g_TG[grow0] = v1;
                    if (colb + 1 == t1) g_TG[grow1] = v3;
                }
            }
            rs[mi][0] += acc0;
            rs[mi][1] += acc1;
        }
    }

    // reduce rowsum across the 4 lanes of each row group
#pragma unroll
    for (int mi = 0; mi < 4; ++mi) {
#pragma unroll
        for (int hh = 0; hh < 2; ++hh) {
            float x = rs[mi][hh];
            x += __shfl_xor_sync(~0u, x, 1);
            x += __shfl_xor_sync(~0u, x, 2);
            if (tq == 0) {
                int row_l = warp_m + mi * 16 + gid + hh * 8;
                red_s[row_l * 4 + (wid >> 2)] = x;
            }
        }
    }
    __syncthreads();
    if (tid < 256) {
        float s = red_s[tid * 4 + 0] + red_s[tid * 4 + 1]
                + red_s[tid * 4 + 2] + red_s[tid * 4 + 3];
        g_PS[ys * NPADROWS + mt * MTILE + tid] = s;
    }
}

// ---------------- 3d) fixup: WLP = target - log(sum of partials) ------------
__global__ void fixup_kernel() {
    int r = blockIdx.x * 256 + threadIdx.x;
    if (r < NROWS) {
        float s = g_PS[r] + g_PS[NPADROWS + r] + g_PS[2 * NPADROWS + r];
        g_WLP[r] = g_TG[r] - logf(s);
    }
}

// ---------------- 4) CKY DP (smem, branch-free online LSE) -------------------
__global__ void dp_kernel(float* __restrict__ out) {
    extern __shared__ float sm[];
    float* T_s   = sm;
    float* SHW_s = sm + L * L * B;
    float* RE_s  = SHW_s + NPAIR * B;

    int tid = threadIdx.x;                 // 640
    int b = tid & 15, i = tid >> 4;

    for (int idx = tid; idx < NPAIR * B; idx += 640) {
        SHW_s[idx] = g_SH[idx] + g_WLP[idx];
        RE_s[idx]  = g_RE[idx];
    }
    if (i == 0) {
        T_s[(0 * L + 1) * B + b] = g_WLP[NPAIR * B + b];
    } else if (i >= 1 && i <= 38) {
        T_s[(i * L + (i + 1)) * B + b] = 0.f;
    }
    __syncthreads();

    for (int gap = 2; gap <= L - 1; ++gap) {
        int n_i = L - gap;
        int j = i + gap;
        if (i < n_i) {
            float m = -1e30f, ssum = 0.f;
            int pik = pair_index(i, i + 1);
#pragma unroll 2
            for (int k = i + 1; k < j; ++k, ++pik) {
                int pkj = pair_index(k, j);
                float sc = T_s[(i * L + k) * B + b] + T_s[(k * L + j) * B + b]
                         + SHW_s[pik * B + b] + RE_s[pkj * B + b];
                float mn = fmaxf(m, sc);
                ssum = fmaf(ssum, __expf(m - mn), __expf(sc - mn));
                m = mn;
            }
            T_s[(i * L + j) * B + b] = m + logf(ssum);
        }
        __syncthreads();
    }

    if (tid < B) out[tid] = T_s[(0 * L + (L - 1)) * B + tid];
}

// ---------------- launcher ----------------
extern "C" void kernel_launch(void* const* d_in, const int* in_sizes, int n_in,
                              void* d_out, int out_size) {
    const float* h        = (const float*)d_in[0];
    const int*   sentence = (const int*)d_in[1];
    const float* Wt1      = (const float*)d_in[2];
    const float* bt1      = (const float*)d_in[3];
    const float* Wt2      = (const float*)d_in[4];
    const float* bt2      = (const float*)d_in[5];
    const float* Ww1      = (const float*)d_in[6];
    const float* bw1      = (const float*)d_in[7];
    const float* Ww2      = (const float*)d_in[8];
    const float* bw2      = (const float*)d_in[9];
    float* out = (float*)d_out;

    static bool attr_set = false;
    if (!attr_set) {
        cudaFuncSetAttribute(dp_kernel, cudaFuncAttributeMaxDynamicSharedMemorySize,
                             DP_SMEM_BYTES);
        cudaFuncSetAttribute(wordmma_kernel, cudaFuncAttributeMaxDynamicSharedMemorySize,
                             WORD_SMEM);
        attr_set = true;
    }

    proj_kernel<<<dim3(10, 4, 4), 256>>>(h, Wt1, Ww1);
    tpair_kernel<<<NPAIR, 256>>>(bt1, Wt2, bt2);
    hiddenb_kernel<<<NROWS, 256>>>(bw1, sentence);
    wconv_kernel<<<dim3(HDIM / 32, (NT_N * NTILE) / 32), dim3(32, 32)>>>(Ww2);
    wordmma_kernel<<<dim3(NMT, YS), 512, WORD_SMEM>>>(bw2);
    fixup_kernel<<<(NROWS + 255) / 256, 256>>>();
    dp_kernel<<<1, 640, DP_SMEM_BYTES>>>(out);
}

// round 10
// speedup vs baseline: 9.4057x; 1.0558x over previous
#include <cuda_runtime.h>
#include <cuda_bf16.h>
#include <math.h>
#include <stdint.h>

#define L 40
#define B 16
#define VSZ 10000
#define FDIM 512
#define HDIM 256
#define NPAIR 780
#define NROWS ((NPAIR + 1) * B)     // 12496
#define NPADROWS 12544              // 49 * 256
#define MTILE 256
#define NTILE 128
#define NMT (NPADROWS / MTILE)      // 49
#define NT_N 79                     // ceil(10000/128)
#define YS 3                        // N-splits

#define DP_SMEM_BYTES ((L * L * B + 2 * NPAIR * B) * 4)   // 202,240 B

// word MMA smem layout (bytes)
#define PITCH 264                    // halves per row (256 + 8 pad)
#define SM_A 0                       // 256 * 264 * 2 = 135168
#define SM_B 135168                  // 128 * 264 * 2 = 67584
#define SM_BIAS 202752               // 128 f32
#define SM_TGT  203264               // 256 i32
#define SM_RED  204288               // 256*4 f32 = 4096
#define WORD_SMEM (SM_RED + 4096)    // 208384

// prep kernel grid partition
#define PREP_TPAIR 780
#define PREP_HID   781
#define PREP_WCONV 2528              // 8 k-tiles x 316 n-tiles
#define PREP_GRID  (PREP_TPAIR + PREP_HID + PREP_WCONV)

// ---------------- device scratch ----------------
__device__ float g_A1[L * B * HDIM];
__device__ float g_A2[L * B * HDIM];
__device__ float g_B1[L * B * HDIM];
__device__ float g_B2[L * B * HDIM];
__device__ float g_SH[NPAIR * B];
__device__ float g_RE[NPAIR * B];
__device__ float g_WLP[NROWS];
__device__ __nv_bfloat16 g_Hb[NPADROWS * HDIM];      // bf16 hidden (pad rows stay 0)
__device__ __nv_bfloat16 g_Wb[NT_N * NTILE * HDIM];  // bf16 Ww2 transposed [n][k]
__device__ float g_PS[YS * NPADROWS];                // partial sum-of-exp
__device__ float g_TG[NPADROWS];                     // target logit
__device__ int   g_TGTI[NPADROWS];                   // target vocab index per row

__device__ __forceinline__ void decode_pair(int p, int& i, int& j) {
    int ii = 0;
    while (p >= (L - 1) - ii) { p -= (L - 1) - ii; ++ii; }
    i = ii;
    j = ii + 1 + p;
}
__device__ __forceinline__ int pair_index(int i, int k) {
    return i * (L - 1) - (i * (i - 1)) / 2 + (k - i - 1);
}
__device__ __forceinline__ float logsig(float x) {
    return fminf(x, 0.f) - log1pf(__expf(-fabsf(x)));
}
__device__ __forceinline__ uint32_t smem_u32(const void* p) {
    uint32_t a;
    asm("{ .reg .u64 t; cvta.to.shared.u64 t, %1; cvt.u32.u64 %0, t; }" : "=r"(a) : "l"(p));
    return a;
}

#define LDSM_X4(r0, r1, r2, r3, addr)                                         \
    asm volatile("ldmatrix.sync.aligned.m8n8.x4.shared.b16 {%0,%1,%2,%3}, [%4];" \
                 : "=r"(r0), "=r"(r1), "=r"(r2), "=r"(r3) : "r"(addr))

#define MMA_BF16(d, a, b0v, b1v)                                              \
    asm volatile("mma.sync.aligned.m16n8k16.row.col.f32.bf16.bf16.f32 "       \
                 "{%0,%1,%2,%3}, {%4,%5,%6,%7}, {%8,%9}, {%0,%1,%2,%3};"      \
                 : "+f"((d)[0]), "+f"((d)[1]), "+f"((d)[2]), "+f"((d)[3])     \
                 : "r"((a)[0]), "r"((a)[1]), "r"((a)[2]), "r"((a)[3]),        \
                   "r"(b0v), "r"(b1v))

// ---------------- 1) projection GEMMs ----------------
__global__ void proj_kernel(const float* __restrict__ h,
                            const float* __restrict__ Wt1,
                            const float* __restrict__ Ww1) {
    __shared__ float As[16][65];
    __shared__ float Bs[16][65];

    int which = blockIdx.z;
    const float* W = (which < 2) ? Ww1 : Wt1;
    const float* Wbase = W + ((which & 1) ? FDIM * HDIM : 0);
    float* C = (which == 0) ? g_A1 : (which == 1) ? g_A2 : (which == 2) ? g_B1 : g_B2;

    int tx = threadIdx.x;
    int m0 = blockIdx.x * 64;
    int n0 = blockIdx.y * 64;
    int tm = (tx >> 4) * 4;
    int tn = (tx & 15) * 4;

    float acc[4][4];
#pragma unroll
    for (int a = 0; a < 4; a++)
#pragma unroll
        for (int c = 0; c < 4; c++) acc[a][c] = 0.f;

    for (int k0 = 0; k0 < FDIM; k0 += 16) {
#pragma unroll
        for (int l = tx; l < 64 * 16; l += 256) {
            int mm = l >> 4, kk = l & 15;
            As[kk][mm] = h[(m0 + mm) * FDIM + k0 + kk];
        }
#pragma unroll
        for (int l = tx; l < 16 * 64; l += 256) {
            int kk = l >> 6, nn = l & 63;
            Bs[kk][nn] = Wbase[(k0 + kk) * HDIM + n0 + nn];
        }
        __syncthreads();
#pragma unroll
        for (int kk = 0; kk < 16; ++kk) {
            float a0 = As[kk][tm], a1 = As[kk][tm + 1], a2 = As[kk][tm + 2], a3 = As[kk][tm + 3];
            float b0 = Bs[kk][tn], b1 = Bs[kk][tn + 1], b2 = Bs[kk][tn + 2], b3 = Bs[kk][tn + 3];
            acc[0][0] = fmaf(a0, b0, acc[0][0]); acc[0][1] = fmaf(a0, b1, acc[0][1]);
            acc[0][2] = fmaf(a0, b2, acc[0][2]); acc[0][3] = fmaf(a0, b3, acc[0][3]);
            acc[1][0] = fmaf(a1, b0, acc[1][0]); acc[1][1] = fmaf(a1, b1, acc[1][1]);
            acc[1][2] = fmaf(a1, b2, acc[1][2]); acc[1][3] = fmaf(a1, b3, acc[1][3]);
            acc[2][0] = fmaf(a2, b0, acc[2][0]); acc[2][1] = fmaf(a2, b1, acc[2][1]);
            acc[2][2] = fmaf(a2, b2, acc[2][2]); acc[2][3] = fmaf(a2, b3, acc[2][3]);
            acc[3][0] = fmaf(a3, b0, acc[3][0]); acc[3][1] = fmaf(a3, b1, acc[3][1]);
            acc[3][2] = fmaf(a3, b2, acc[3][2]); acc[3][3] = fmaf(a3, b3, acc[3][3]);
        }
        __syncthreads();
    }
#pragma unroll
    for (int a = 0; a < 4; a++)
#pragma unroll
        for (int c = 0; c < 4; c++)
            C[(m0 + tm + a) * HDIM + n0 + tn + c] = acc[a][c];
}

// ---------------- 2) fused prep: tpair | hiddenb | wconv (grid-partitioned) --
__global__ void prep_kernel(const float* __restrict__ bt1,
                            const float* __restrict__ Wt2,
                            const float* __restrict__ bt2,
                            const float* __restrict__ bw1,
                            const int* __restrict__ sentence,
                            const float* __restrict__ Ww2) {
    __shared__ float t[32][33];
    int blk = blockIdx.x;
    int tid = threadIdx.x;

    if (blk < PREP_TPAIR) {
        // ---- transition MLP ----
        int p = blk;
        int wid = tid >> 5, lane = tid & 31;
        int i, j;
        decode_pair(p, i, j);
#pragma unroll
        for (int sub = 0; sub < 2; ++sub) {
            int b = wid * 2 + sub;
            const float* r1 = g_B1 + (i * B + b) * HDIM;
            const float* r2 = g_B2 + (j * B + b) * HDIM;
            float acc = 0.f;
#pragma unroll
            for (int hh = lane; hh < HDIM; hh += 32) {
                float hv = tanhf(r1[hh] + r2[hh] + bt1[hh]);
                acc = fmaf(hv, Wt2[hh], acc);
            }
            acc += __shfl_xor_sync(~0u, acc, 16);
            acc += __shfl_xor_sync(~0u, acc, 8);
            acc += __shfl_xor_sync(~0u, acc, 4);
            acc += __shfl_xor_sync(~0u, acc, 2);
            acc += __shfl_xor_sync(~0u, acc, 1);
            if (lane == 0) {
                float tt = acc + bt2[0];
                g_SH[p * B + b] = logsig(-tt);
                g_RE[p * B + b] = logsig(tt);
            }
        }
    } else if (blk < PREP_TPAIR + PREP_HID) {
        // ---- bf16 hidden + per-row target ----
        int r = blk - PREP_TPAIR;
        int p = r, b = tid;  // we remap below: r is pair index, loop over batch rows
        // one block handles one pair (16 rows x 256 h): tid = h index
        int i = 0, j = 0;
        if (p < NPAIR) decode_pair(p, i, j);
#pragma unroll
        for (int bb = 0; bb < B; ++bb) {
            float v = tanhf(g_A1[(i * B + bb) * HDIM + tid]
                          + g_A2[(j * B + bb) * HDIM + tid] + bw1[tid]);
            g_Hb[(p * B + bb) * HDIM + tid] = __float2bfloat16(v);
        }
        if (tid < B) {
            int tg;
            if (p == NPAIR) tg = sentence[1 * B + tid];
            else {
                int j1 = (j + 1 < L) ? (j + 1) : (L - 1);
                tg = sentence[j1 * B + tid];
            }
            g_TGTI[p * B + tid] = tg;
        }
        (void)b;
    } else {
        // ---- transpose+convert Ww2 -> g_Wb[n][k] bf16 ----
        int tile = blk - PREP_TPAIR - PREP_HID;      // 0..2527
        int kt = tile & 7;                            // 8 k-tiles
        int nt = tile >> 3;                           // 316 n-tiles
        int tx = tid & 31, ty0 = tid >> 5;            // 8 rows per pass
#pragma unroll
        for (int rr = 0; rr < 4; ++rr) {
            int ty = ty0 + rr * 8;
            int k = kt * 32 + ty, n = nt * 32 + tx;
            t[ty][tx] = (n < VSZ) ? Ww2[k * VSZ + n] : 0.f;
        }
        __syncthreads();
#pragma unroll
        for (int rr = 0; rr < 4; ++rr) {
            int ty = ty0 + rr * 8;
            int n2 = nt * 32 + ty, k2 = kt * 32 + tx;
            g_Wb[n2 * HDIM + k2] = __float2bfloat16(t[tx][ty]);
        }
    }
}

// ---------------- 3) word GEMM via mma.sync bf16 + fused softmax pieces ------
__global__ __launch_bounds__(512)
void wordmma_kernel(const float* __restrict__ bw2) {
    extern __shared__ char smem[];
    uint32_t sb = smem_u32(smem);
    float* bias_s = (float*)(smem + SM_BIAS);
    int*   tgt_s  = (int*)(smem + SM_TGT);
    float* red_s  = (float*)(smem + SM_RED);

    int tid = threadIdx.x;                 // 512
    int wid = tid >> 5, lane = tid & 31;
    int tq = lane & 3, gid = lane >> 2;
    int mt = blockIdx.x, ys = blockIdx.y;
    int warp_m = (wid & 3) * 64;           // 4 m-groups
    int warp_n = (wid >> 2) * 32;          // 4 n-groups

    // load A tile (256 x 256 bf16) into smem, pitch 264 halves
    {
        const __nv_bfloat16* hb = g_Hb + (size_t)mt * MTILE * HDIM;
        for (int idx = tid; idx < 256 * 32; idx += 512) {
            int r = idx >> 5, seg = idx & 31;
            uint4 v = *(const uint4*)(hb + r * HDIM + seg * 8);
            *(uint4*)(smem + SM_A + (r * PITCH + seg * 8) * 2) = v;
        }
    }
    if (tid < 256) tgt_s[tid] = g_TGTI[mt * MTILE + tid];

    float rs[4][2];
#pragma unroll
    for (int mi = 0; mi < 4; ++mi) { rs[mi][0] = 0.f; rs[mi][1] = 0.f; }

    int nt0 = (ys * NT_N) / YS, nt1 = ((ys + 1) * NT_N) / YS;

    // prologue: prefetch first B tile into registers (8 x uint4 per thread)
    uint4 pre[8];
    {
        const __nv_bfloat16* wb = g_Wb + (size_t)nt0 * NTILE * HDIM;
#pragma unroll
        for (int u = 0; u < 8; ++u) {
            int idx = tid + u * 512;
            int r = idx >> 5, seg = idx & 31;
            pre[u] = *(const uint4*)(wb + r * HDIM + seg * 8);
        }
    }

    for (int nt = nt0; nt < nt1; ++nt) {
        int n0 = nt * NTILE;
        __syncthreads();    // previous iter's smem B reads done (also orders A stores)
#pragma unroll
        for (int u = 0; u < 8; ++u) {
            int idx = tid + u * 512;
            int r = idx >> 5, seg = idx & 31;
            *(uint4*)(smem + SM_B + (r * PITCH + seg * 8) * 2) = pre[u];
        }
        if (tid < 128) {
            int col = n0 + tid;
            bias_s[tid] = (col < VSZ) ? bw2[col] : 0.f;
        }
        __syncthreads();

        // prefetch next B tile into registers (overlaps with MMA below)
        if (nt + 1 < nt1) {
            const __nv_bfloat16* wb = g_Wb + (size_t)(nt + 1) * NTILE * HDIM;
#pragma unroll
            for (int u = 0; u < 8; ++u) {
                int idx = tid + u * 512;
                int r = idx >> 5, seg = idx & 31;
                pre[u] = *(const uint4*)(wb + r * HDIM + seg * 8);
            }
        }

        float d[4][4][4];
#pragma unroll
        for (int mi = 0; mi < 4; ++mi)
#pragma unroll
            for (int ni = 0; ni < 4; ++ni)
#pragma unroll
                for (int r = 0; r < 4; ++r) d[mi][ni][r] = 0.f;

#pragma unroll
        for (int ks = 0; ks < 16; ++ks) {
            int k0 = ks * 16;
            uint32_t a[4][4];
#pragma unroll
            for (int mi = 0; mi < 4; ++mi) {
                uint32_t row = warp_m + mi * 16 + (lane & 15);
                uint32_t col = k0 + ((lane >> 4) << 3);
                uint32_t ad = sb + SM_A + (row * PITCH + col) * 2;
                LDSM_X4(a[mi][0], a[mi][1], a[mi][2], a[mi][3], ad);
            }
#pragma unroll
            for (int nq = 0; nq < 2; ++nq) {
                uint32_t nrow = warp_n + nq * 16 + (lane & 7) + ((lane >> 4) << 3);
                uint32_t col = k0 + (((lane >> 3) & 1) << 3);
                uint32_t bd = sb + SM_B + (nrow * PITCH + col) * 2;
                uint32_t bfr[4];
                LDSM_X4(bfr[0], bfr[1], bfr[2], bfr[3], bd);
#pragma unroll
                for (int mi = 0; mi < 4; ++mi) {
                    MMA_BF16(d[mi][nq * 2 + 0], a[mi], bfr[0], bfr[1]);
                    MMA_BF16(d[mi][nq * 2 + 1], a[mi], bfr[2], bfr[3]);
                }
            }
        }

        // epilogue: bias + exp-sum + target gather
#pragma unroll
        for (int mi = 0; mi < 4; ++mi) {
            int r0 = warp_m + mi * 16 + gid;
            int r1 = r0 + 8;
            int t0 = tgt_s[r0], t1 = tgt_s[r1];
            int grow0 = mt * MTILE + r0, grow1 = mt * MTILE + r1;
            float acc0 = 0.f, acc1 = 0.f;
#pragma unroll
            for (int ni = 0; ni < 4; ++ni) {
                int cl = warp_n + ni * 8 + tq * 2;
                int colb = n0 + cl;
                float bia0 = bias_s[cl], bia1 = bias_s[cl + 1];
                float v0 = d[mi][ni][0] + bia0;
                float v1 = d[mi][ni][1] + bia1;
                float v2 = d[mi][ni][2] + bia0;
                float v3 = d[mi][ni][3] + bia1;
                if (colb < VSZ) {
                    acc0 += __expf(v0);
                    acc1 += __expf(v2);
                    if (colb == t0) g_TG[grow0] = v0;
                    if (colb == t1) g_TG[grow1] = v2;
                }
                if (colb + 1 < VSZ) {
                    acc0 += __expf(v1);
                    acc1 += __expf(v3);
                    if (colb + 1 == t0) g_TG[grow0] = v1;
                    if (colb + 1 == t1) g_TG[grow1] = v3;
                }
            }
            rs[mi][0] += acc0;
            rs[mi][1] += acc1;
        }
    }

    // reduce rowsum across the 4 lanes of each row group
#pragma unroll
    for (int mi = 0; mi < 4; ++mi) {
#pragma unroll
        for (int hh = 0; hh < 2; ++hh) {
            float x = rs[mi][hh];
            x += __shfl_xor_sync(~0u, x, 1);
            x += __shfl_xor_sync(~0u, x, 2);
            if (tq == 0) {
                int row_l = warp_m + mi * 16 + gid + hh * 8;
                red_s[row_l * 4 + (wid >> 2)] = x;
            }
        }
    }
    __syncthreads();
    if (tid < 256) {
        float s = red_s[tid * 4 + 0] + red_s[tid * 4 + 1]
                + red_s[tid * 4 + 2] + red_s[tid * 4 + 3];
        g_PS[ys * NPADROWS + mt * MTILE + tid] = s;
    }
}

// ---------------- 3d) fixup: WLP = target - log(sum of partials) ------------
__global__ void fixup_kernel() {
    int r = blockIdx.x * 256 + threadIdx.x;
    if (r < NROWS) {
        float s = g_PS[r] + g_PS[NPADROWS + r] + g_PS[2 * NPADROWS + r];
        g_WLP[r] = g_TG[r] - logf(s);
    }
}

// ---------------- 4) CKY DP (smem, two-chain online LSE) ---------------------
__global__ void dp_kernel(float* __restrict__ out) {
    extern __shared__ float sm[];
    float* T_s   = sm;
    float* SHW_s = sm + L * L * B;
    float* RE_s  = SHW_s + NPAIR * B;

    int tid = threadIdx.x;                 // 640
    int b = tid & 15, i = tid >> 4;

    for (int idx = tid; idx < NPAIR * B; idx += 640) {
        SHW_s[idx] = g_SH[idx] + g_WLP[idx];
        RE_s[idx]  = g_RE[idx];
    }
    if (i == 0) {
        T_s[(0 * L + 1) * B + b] = g_WLP[NPAIR * B + b];
    } else if (i >= 1 && i <= 38) {
        T_s[(i * L + (i + 1)) * B + b] = 0.f;
    }
    __syncthreads();

    for (int gap = 2; gap <= L - 1; ++gap) {
        int n_i = L - gap;
        int j = i + gap;
        if (i < n_i) {
            float m0 = -1e30f, s0 = 0.f, m1 = -1e30f, s1 = 0.f;
            int k = i + 1;
            int pik = pair_index(i, k);
            for (; k + 1 < j; k += 2, pik += 2) {
                int pkj0 = pair_index(k, j);
                int pkj1 = pair_index(k + 1, j);
                float sc0 = T_s[(i * L + k) * B + b] + T_s[(k * L + j) * B + b]
                          + SHW_s[pik * B + b] + RE_s[pkj0 * B + b];
                float sc1 = T_s[(i * L + k + 1) * B + b] + T_s[((k + 1) * L + j) * B + b]
                          + SHW_s[(pik + 1) * B + b] + RE_s[pkj1 * B + b];
                float mn0 = fmaxf(m0, sc0);
                s0 = fmaf(s0, __expf(m0 - mn0), __expf(sc0 - mn0));
                m0 = mn0;
                float mn1 = fmaxf(m1, sc1);
                s1 = fmaf(s1, __expf(m1 - mn1), __expf(sc1 - mn1));
                m1 = mn1;
            }
            if (k < j) {
                int pkj0 = pair_index(k, j);
                float sc0 = T_s[(i * L + k) * B + b] + T_s[(k * L + j) * B + b]
                          + SHW_s[pik * B + b] + RE_s[pkj0 * B + b];
                float mn0 = fmaxf(m0, sc0);
                s0 = fmaf(s0, __expf(m0 - mn0), __expf(sc0 - mn0));
                m0 = mn0;
            }
            float mn = fmaxf(m0, m1);
            float ss = s0 * __expf(m0 - mn) + s1 * __expf(m1 - mn);
            T_s[(i * L + j) * B + b] = mn + logf(ss);
        }
        __syncthreads();
    }

    if (tid < B) out[tid] = T_s[(0 * L + (L - 1)) * B + tid];
}

// ---------------- launcher ----------------
extern "C" void kernel_launch(void* const* d_in, const int* in_sizes, int n_in,
                              void* d_out, int out_size) {
    const float* h        = (const float*)d_in[0];
    const int*   sentence = (const int*)d_in[1];
    const float* Wt1      = (const float*)d_in[2];
    const float* bt1      = (const float*)d_in[3];
    const float* Wt2      = (const float*)d_in[4];
    const float* bt2      = (const float*)d_in[5];
    const float* Ww1      = (const float*)d_in[6];
    const float* bw1      = (const float*)d_in[7];
    const float* Ww2      = (const float*)d_in[8];
    const float* bw2      = (const float*)d_in[9];
    float* out = (float*)d_out;

    static bool attr_set = false;
    if (!attr_set) {
        cudaFuncSetAttribute(dp_kernel, cudaFuncAttributeMaxDynamicSharedMemorySize,
                             DP_SMEM_BYTES);
        cudaFuncSetAttribute(wordmma_kernel, cudaFuncAttributeMaxDynamicSharedMemorySize,
                             WORD_SMEM);
        attr_set = true;
    }

    proj_kernel<<<dim3(10, 4, 4), 256>>>(h, Wt1, Ww1);
    prep_kernel<<<PREP_GRID, 256>>>(bt1, Wt2, bt2, bw1, sentence, Ww2);
    wordmma_kernel<<<dim3(NMT, YS), 512, WORD_SMEM>>>(bw2);
    fixup_kernel<<<(NROWS + 255) / 256, 256>>>();
    dp_kernel<<<1, 640, DP_SMEM_BYTES>>>(out);
}